// round 2
// baseline (speedup 1.0000x reference)
#include <cuda_runtime.h>
#include <math.h>

// ---------------- problem constants ----------------
constexpr int kB    = 4;
constexpr int kS    = 1000;
constexpr int kHID  = 1024;
constexpr int kNH   = 16;
constexpr int kDK   = 64;
constexpr int kFFH  = 2048;
constexpr int kVOC  = 32000;
constexpr int kROWS = kB * kS;     // 4000
constexpr int kBH   = kB * kNH;    // 64

// ---------------- device scratch (no allocations allowed) ----------------
__device__ float g_pe[kHID];
__device__ float g_x   [kROWS * kHID];
__device__ float g_q   [kBH * kS * kDK];
__device__ float g_k   [kBH * kS * kDK];
__device__ float g_v   [kBH * kS * kDK];
__device__ float g_scores[(size_t)kBH * kS * kS];   // 256 MB
__device__ float g_attn[kROWS * kHID];
__device__ float g_x1  [kROWS * kHID];
__device__ float g_h   [kROWS * kFFH];
__device__ float g_ff  [kROWS * kHID];
__device__ float g_x2  [kROWS * kHID];
__device__ float g_wq  [kHID * kHID];
__device__ float g_wk  [kHID * kHID];
__device__ float g_wv  [kHID * kHID];

// ---------------- positional encoding (source-bug constant vector) ----------------
// pe[2j] = sin(tmp_j), pe[2j+1] = cos(tmp_j), tmp_j = 999 / 10000^(2j/1024)
__global__ void pe_kernel() {
    int c = threadIdx.x;                     // 0..1023
    int i = c & ~1;                          // even index
    double tmp = 999.0 * exp(-(double)i / 1024.0 * log(10000.0));
    g_pe[c] = (c & 1) ? (float)cos(tmp) : (float)sin(tmp);
}

// x[row] = emb[token[row]] + pe
__global__ void embed_kernel(const int* __restrict__ tok, const float* __restrict__ emb) {
    int row = blockIdx.x;
    int t = tok[row];
    const float4* e = (const float4*)(emb + (size_t)t * kHID);
    const float4* p = (const float4*)g_pe;
    float4* xo = (float4*)(g_x + (size_t)row * kHID);
    int c = threadIdx.x;                     // 256 threads, HID/4 = 256 float4
    float4 a = e[c], b = p[c];
    xo[c] = make_float4(a.x + b.x, a.y + b.y, a.z + b.z, a.w + b.w);
}

// repack W[n][h][d] -> Wp[h][n*64+d]  (so QKV becomes a plain [HID,HID] GEMM)
__global__ void pack_w_kernel(const float* __restrict__ W, float* __restrict__ out) {
    int idx = blockIdx.x * blockDim.x + threadIdx.x;   // over HID*HID
    if (idx < kHID * kHID) {
        int h = idx >> 10;
        int col = idx & 1023;
        int n = col >> 6, d = col & 63;
        out[idx] = W[((size_t)n * kHID + h) * kDK + d];
    }
}

// ---------------- generic tiled SGEMM: C = A[M,K] @ B[K,N] + bias ----------------
// EPI: 0 = plain, 1 = relu, 2 = scatter to q/k/v layout [b][n][s][d]
// BM=128, BN=128, BK=16, 256 threads, 8x8 per thread.
// Requires: N % 128 == 0, K % 16 == 0. M edge guarded.
template<int EPI>
__global__ __launch_bounds__(256)
void sgemm_kernel(const float* __restrict__ A, const float* __restrict__ Bm,
                  const float* __restrict__ bias, float* __restrict__ C,
                  int M, int N, int K) {
    __shared__ float As[16][128 + 4];   // [k][m]
    __shared__ float Bs[16][128];       // [k][n]
    int tid = threadIdx.x;
    int tr = tid >> 4, tc = tid & 15;
    int m0 = blockIdx.y * 128, n0 = blockIdx.x * 128;

    float acc[8][8] = {};
    for (int k0 = 0; k0 < K; k0 += 16) {
#pragma unroll
        for (int i = 0; i < 2; i++) {
            int idx = tid + i * 256;             // 512 float4 for A tile
            int ar = idx >> 2;                   // 0..127
            int ac = (idx & 3) << 2;             // 0,4,8,12
            float4 va = (m0 + ar < M)
                ? *(const float4*)&A[(size_t)(m0 + ar) * K + k0 + ac]
                : make_float4(0.f, 0.f, 0.f, 0.f);
            As[ac + 0][ar] = va.x; As[ac + 1][ar] = va.y;
            As[ac + 2][ar] = va.z; As[ac + 3][ar] = va.w;

            int br = idx >> 5;                   // 0..15
            int bc = (idx & 31) << 2;            // 0..124
            *(float4*)&Bs[br][bc] = *(const float4*)&Bm[(size_t)(k0 + br) * N + n0 + bc];
        }
        __syncthreads();
#pragma unroll
        for (int k = 0; k < 16; k++) {
            float ra[8], rb[8];
#pragma unroll
            for (int i = 0; i < 8; i++) ra[i] = As[k][tr * 8 + i];
#pragma unroll
            for (int j = 0; j < 8; j++) rb[j] = Bs[k][tc * 8 + j];
#pragma unroll
            for (int i = 0; i < 8; i++)
#pragma unroll
                for (int j = 0; j < 8; j++) acc[i][j] += ra[i] * rb[j];
        }
        __syncthreads();
    }

#pragma unroll
    for (int i = 0; i < 8; i++) {
        int row = m0 + tr * 8 + i;
        if (row >= M) continue;
#pragma unroll
        for (int j = 0; j < 8; j++) {
            int col = n0 + tc * 8 + j;
            float vv = acc[i][j] + bias[col];
            if (EPI == 1) vv = fmaxf(vv, 0.f);
            if (EPI == 2) {
                int b = row / kS, s = row % kS;
                int n = col >> 6, d = col & 63;
                C[(((size_t)(b * kNH + n)) * kS + s) * kDK + d] = vv;
            } else {
                C[(size_t)row * N + col] = vv;
            }
        }
    }
}

// ---------------- attention scores: w[s][t] = floor((k_s . q_t)/8), mask t>s ----------------
__global__ __launch_bounds__(256)
void scores_kernel() {
    int bh = blockIdx.z;
    int s0 = blockIdx.y * 64, t0 = blockIdx.x * 64;
    if (t0 > s0 + 63) return;   // tile fully masked (softmax writes zeros there)

    __shared__ float Ks[64][68];   // [d][s]
    __shared__ float Qs[64][68];   // [d][t]
    const float* kp = g_k + (size_t)bh * kS * kDK;
    const float* qp = g_q + (size_t)bh * kS * kDK;
    int tid = threadIdx.x;
#pragma unroll
    for (int i = 0; i < 4; i++) {
        int idx = tid + i * 256;            // 1024 float4
        int r = idx >> 4;                   // 0..63
        int c = (idx & 15) << 2;            // 0..60
        float4 vk = (s0 + r < kS) ? *(const float4*)&kp[(size_t)(s0 + r) * kDK + c]
                                  : make_float4(0.f, 0.f, 0.f, 0.f);
        float4 vq = (t0 + r < kS) ? *(const float4*)&qp[(size_t)(t0 + r) * kDK + c]
                                  : make_float4(0.f, 0.f, 0.f, 0.f);
        Ks[c + 0][r] = vk.x; Ks[c + 1][r] = vk.y; Ks[c + 2][r] = vk.z; Ks[c + 3][r] = vk.w;
        Qs[c + 0][r] = vq.x; Qs[c + 1][r] = vq.y; Qs[c + 2][r] = vq.z; Qs[c + 3][r] = vq.w;
    }
    __syncthreads();

    int tr = tid >> 4, tc = tid & 15;
    float acc[4][4] = {};
#pragma unroll
    for (int d = 0; d < 64; d++) {
        float ra[4], rb[4];
#pragma unroll
        for (int i = 0; i < 4; i++) ra[i] = Ks[d][tr * 4 + i];
#pragma unroll
        for (int j = 0; j < 4; j++) rb[j] = Qs[d][tc * 4 + j];
#pragma unroll
        for (int i = 0; i < 4; i++)
#pragma unroll
            for (int j = 0; j < 4; j++) acc[i][j] += ra[i] * rb[j];
    }
#pragma unroll
    for (int i = 0; i < 4; i++) {
        int s = s0 + tr * 4 + i;
        if (s >= kS) continue;
#pragma unroll
        for (int j = 0; j < 4; j++) {
            int t = t0 + tc * 4 + j;
            if (t >= kS) continue;
            float w = (t > s) ? __int_as_float(0xff800000)      // -inf
                              : floorf(acc[i][j] * 0.125f);      // /sqrt(64) exact
            g_scores[((size_t)bh * kS + s) * kS + t] = w;
        }
    }
}

// ---------------- row softmax over t <= s; zeros for t > s ----------------
// Single expf sweep: cache e = exp(w - m) in place during the sum pass.
__global__ __launch_bounds__(256)
void softmax_kernel() {
    int r = blockIdx.x;                 // bh*S + s
    int s = r % kS;
    float* row = g_scores + (size_t)r * kS;
    int tid = threadIdx.x;
    __shared__ float red[256];

    float m = -1e30f;
    for (int t = tid; t <= s; t += 256) m = fmaxf(m, row[t]);
    red[tid] = m; __syncthreads();
    for (int o = 128; o; o >>= 1) { if (tid < o) red[tid] = fmaxf(red[tid], red[tid + o]); __syncthreads(); }
    m = red[0]; __syncthreads();

    float ls = 0.f;
    for (int t = tid; t <= s; t += 256) {
        float e = expf(row[t] - m);
        row[t] = e;                     // cache exp; scaled below
        ls += e;
    }
    red[tid] = ls; __syncthreads();
    for (int o = 128; o; o >>= 1) { if (tid < o) red[tid] += red[tid + o]; __syncthreads(); }
    float inv = 1.f / red[0];
    __syncthreads();

    for (int t = tid; t < kS; t += 256) row[t] = (t <= s) ? row[t] * inv : 0.f;
}

// ---------------- attn = score @ V, scattered to concat-head layout ----------------
__global__ __launch_bounds__(256)
void pv_kernel() {
    int bh = blockIdx.y;
    int s0 = blockIdx.x * 64;
    const float* sc = g_scores + (size_t)bh * kS * kS;
    const float* vp = g_v + (size_t)bh * kS * kDK;
    __shared__ float Ss[32][68];   // [t][s]
    __shared__ float Vs[32][68];   // [t][d]
    int tid = threadIdx.x;
    int tr = tid >> 4, tc = tid & 15;
    float acc[4][4] = {};
    int kend = min(kS, s0 + 64);   // scores are zero for t > s

    for (int t0 = 0; t0 < kend; t0 += 32) {
#pragma unroll
        for (int i = 0; i < 2; i++) {
            int idx = tid + i * 256;            // 512 float4 per array
            int r = idx >> 3;                   // score s-row 0..63
            int c = (idx & 7) << 2;             // score t 0..28
            int s = s0 + r, t = t0 + c;
            float4 vv = (s < kS && t < kS)
                ? *(const float4*)&sc[(size_t)s * kS + t]
                : make_float4(0.f, 0.f, 0.f, 0.f);
            Ss[c + 0][r] = vv.x; Ss[c + 1][r] = vv.y; Ss[c + 2][r] = vv.z; Ss[c + 3][r] = vv.w;

            int vr = idx >> 4;                  // v t-row 0..31
            int vc = (idx & 15) << 2;           // d
            float4 vv2 = (t0 + vr < kS)
                ? *(const float4*)&vp[(size_t)(t0 + vr) * kDK + vc]
                : make_float4(0.f, 0.f, 0.f, 0.f);
            *(float4*)&Vs[vr][vc] = vv2;
        }
        __syncthreads();
#pragma unroll
        for (int k = 0; k < 32; k++) {
            float ra[4], rb[4];
#pragma unroll
            for (int i = 0; i < 4; i++) ra[i] = Ss[k][tr * 4 + i];
#pragma unroll
            for (int j = 0; j < 4; j++) rb[j] = Vs[k][tc * 4 + j];
#pragma unroll
            for (int i = 0; i < 4; i++)
#pragma unroll
                for (int j = 0; j < 4; j++) acc[i][j] += ra[i] * rb[j];
        }
        __syncthreads();
    }

    int b = bh >> 4, n = bh & 15;
#pragma unroll
    for (int i = 0; i < 4; i++) {
        int s = s0 + tr * 4 + i;
        if (s >= kS) continue;
#pragma unroll
        for (int j = 0; j < 4; j++) {
            g_attn[((size_t)(b * kS + s)) * kHID + n * kDK + tc * 4 + j] = acc[i][j];
        }
    }
}

// ---------------- out = LayerNorm(x + delta) * g + b ----------------
__global__ __launch_bounds__(256)
void add_ln_kernel(const float* __restrict__ xin, const float* __restrict__ dl,
                   const float* __restrict__ g, const float* __restrict__ b,
                   float* __restrict__ out) {
    int row = blockIdx.x;
    int tid = threadIdx.x;
    const float* xr = xin + (size_t)row * kHID;
    const float* dr = dl  + (size_t)row * kHID;
    __shared__ float red[256];

    float v[4]; float ls = 0.f;
#pragma unroll
    for (int i = 0; i < 4; i++) { int c = tid + i * 256; v[i] = xr[c] + dr[c]; ls += v[i]; }
    red[tid] = ls; __syncthreads();
    for (int o = 128; o; o >>= 1) { if (tid < o) red[tid] += red[tid + o]; __syncthreads(); }
    float mu = red[0] * (1.f / kHID);
    __syncthreads();

    float lv = 0.f;
#pragma unroll
    for (int i = 0; i < 4; i++) { float d = v[i] - mu; lv += d * d; }
    red[tid] = lv; __syncthreads();
    for (int o = 128; o; o >>= 1) { if (tid < o) red[tid] += red[tid + o]; __syncthreads(); }
    float rstd = 1.f / sqrtf(red[0] * (1.f / kHID) + 1e-5f);

    float* orow = out + (size_t)row * kHID;
#pragma unroll
    for (int i = 0; i < 4; i++) {
        int c = tid + i * 256;
        orow[c] = (v[i] - mu) * rstd * g[c] + b[c];
    }
}

// ---------------- launcher ----------------
extern "C" void kernel_launch(void* const* d_in, const int* in_sizes, int n_in,
                              void* d_out, int out_size) {
    const int*   tok  = (const int*)  d_in[0];
    const float* emb  = (const float*)d_in[1];
    const float* Wq   = (const float*)d_in[2];
    const float* bq   = (const float*)d_in[3];
    const float* Wk   = (const float*)d_in[4];
    const float* bk   = (const float*)d_in[5];
    const float* Wv   = (const float*)d_in[6];
    const float* bv   = (const float*)d_in[7];
    const float* Wc   = (const float*)d_in[8];
    const float* bc   = (const float*)d_in[9];
    const float* ln1g = (const float*)d_in[10];
    const float* ln1b = (const float*)d_in[11];
    const float* W1   = (const float*)d_in[12];
    const float* b1   = (const float*)d_in[13];
    const float* W2   = (const float*)d_in[14];
    const float* b2   = (const float*)d_in[15];
    const float* ln2g = (const float*)d_in[16];
    const float* ln2b = (const float*)d_in[17];
    const float* Wlog = (const float*)d_in[18];
    const float* blog = (const float*)d_in[19];
    float* out = (float*)d_out;

    float *px, *pq, *pk, *pv, *pattn, *px1, *ph, *pff, *px2, *pwq, *pwk, *pwv;
    cudaGetSymbolAddress((void**)&px,   g_x);
    cudaGetSymbolAddress((void**)&pq,   g_q);
    cudaGetSymbolAddress((void**)&pk,   g_k);
    cudaGetSymbolAddress((void**)&pv,   g_v);
    cudaGetSymbolAddress((void**)&pattn,g_attn);
    cudaGetSymbolAddress((void**)&px1,  g_x1);
    cudaGetSymbolAddress((void**)&ph,   g_h);
    cudaGetSymbolAddress((void**)&pff,  g_ff);
    cudaGetSymbolAddress((void**)&px2,  g_x2);
    cudaGetSymbolAddress((void**)&pwq,  g_wq);
    cudaGetSymbolAddress((void**)&pwk,  g_wk);
    cudaGetSymbolAddress((void**)&pwv,  g_wv);

    // 1. positional encoding + embedding
    pe_kernel<<<1, 1024>>>();
    embed_kernel<<<kROWS, 256>>>(tok, emb);

    // 2. repack per-head QKV weights into [HID, HID]
    pack_w_kernel<<<(kHID * kHID + 255) / 256, 256>>>(Wq, pwq);
    pack_w_kernel<<<(kHID * kHID + 255) / 256, 256>>>(Wk, pwk);
    pack_w_kernel<<<(kHID * kHID + 255) / 256, 256>>>(Wv, pwv);

    // 3. QKV projections (scatter epilogue to [b][n][s][d])
    dim3 gQ(kHID / 128, (kROWS + 127) / 128);
    sgemm_kernel<2><<<gQ, 256>>>(px, pwq, bq, pq, kROWS, kHID, kHID);
    sgemm_kernel<2><<<gQ, 256>>>(px, pwk, bk, pk, kROWS, kHID, kHID);
    sgemm_kernel<2><<<gQ, 256>>>(px, pwv, bv, pv, kROWS, kHID, kHID);

    // 4. attention
    scores_kernel<<<dim3(16, 16, kBH), 256>>>();
    softmax_kernel<<<kBH * kS, 256>>>();
    pv_kernel<<<dim3(16, kBH), 256>>>();

    // 5. output projection + residual + LN1
    sgemm_kernel<0><<<dim3(kHID / 128, (kROWS + 127) / 128), 256>>>(pattn, Wc, bc, pff, kROWS, kHID, kHID);
    add_ln_kernel<<<kROWS, 256>>>(px, pff, ln1g, ln1b, px1);

    // 6. feed-forward + residual + LN2
    sgemm_kernel<1><<<dim3(kFFH / 128, (kROWS + 127) / 128), 256>>>(px1, W1, b1, ph, kROWS, kFFH, kHID);
    sgemm_kernel<0><<<dim3(kHID / 128, (kROWS + 127) / 128), 256>>>(ph, W2, b2, pff, kROWS, kHID, kFFH);
    add_ln_kernel<<<kROWS, 256>>>(px1, pff, ln2g, ln2b, px2);

    // 7. logits (dominant GEMM) -> d_out
    sgemm_kernel<0><<<dim3(kVOC / 128, (kROWS + 127) / 128), 256>>>(px2, Wlog, blog, out, kROWS, kVOC, kHID);

    (void)in_sizes; (void)n_in; (void)out_size;
}

// round 5
// speedup vs baseline: 1.7523x; 1.7523x over previous
#include <cuda_runtime.h>
#include <cuda_bf16.h>
#include <math.h>
#include <stdint.h>

// ---------------- problem constants ----------------
constexpr int kB    = 4;
constexpr int kS    = 1000;
constexpr int kHID  = 1024;
constexpr int kNH   = 16;
constexpr int kDK   = 64;
constexpr int kFFH  = 2048;
constexpr int kVOC  = 32000;
constexpr int kROWS = kB * kS;     // 4000
constexpr int kBH   = kB * kNH;    // 64

// ---------------- device scratch (no allocations allowed) ----------------
// NOTE: bf16 split buffers ALIAS g_scores (time-disjoint usage; see launcher).
// Static footprint identical to the known-good R2 build (~432 MB).
__device__ float g_pe[kHID];
__device__ float g_x   [kROWS * kHID];
__device__ float g_q   [kBH * kS * kDK];
__device__ float g_k   [kBH * kS * kDK];
__device__ float g_v   [kBH * kS * kDK];
__device__ __align__(256) float g_scores[(size_t)kBH * kS * kS];   // 256 MB (also hosts split buffers)
__device__ float g_attn[kROWS * kHID];
__device__ float g_x1  [kROWS * kHID];
__device__ float g_h   [kROWS * kFFH];
__device__ float g_ff  [kROWS * kHID];
__device__ float g_x2  [kROWS * kHID];
__device__ float g_wq  [kHID * kHID];
__device__ float g_wk  [kHID * kHID];
__device__ float g_wv  [kHID * kHID];

// byte offsets of split buffers inside g_scores (all 16B-aligned)
constexpr size_t kOffBhi = 0;                                        // 65,536,000 B
constexpr size_t kOffBlo = (size_t)kHID * kVOC * 2;                  // +65,536,000
constexpr size_t kOffAhi = kOffBlo + (size_t)kHID * kVOC * 2;        // 131,072,000
constexpr size_t kOffAlo = kOffAhi + (size_t)kROWS * kFFH * 2;       // +16,384,000
static_assert(kOffAlo + (size_t)kROWS * kFFH * 2 <= (size_t)kBH * kS * kS * 4, "pool overflow");

// ---------------- positional encoding (source-bug constant vector) ----------------
__global__ void pe_kernel() {
    int c = threadIdx.x;                     // 0..1023
    int i = c & ~1;                          // even index
    double tmp = 999.0 * exp(-(double)i / 1024.0 * log(10000.0));
    g_pe[c] = (c & 1) ? (float)cos(tmp) : (float)sin(tmp);
}

// x[row] = emb[token[row]] + pe
__global__ void embed_kernel(const int* __restrict__ tok, const float* __restrict__ emb) {
    int row = blockIdx.x;
    int t = tok[row];
    const float4* e = (const float4*)(emb + (size_t)t * kHID);
    const float4* p = (const float4*)g_pe;
    float4* xo = (float4*)(g_x + (size_t)row * kHID);
    int c = threadIdx.x;                     // 256 threads, HID/4 = 256 float4
    float4 a = e[c], b = p[c];
    xo[c] = make_float4(a.x + b.x, a.y + b.y, a.z + b.z, a.w + b.w);
}

// repack W[n][h][d] -> Wp[h][n*64+d]
__global__ void pack_w_kernel(const float* __restrict__ W, float* __restrict__ out) {
    int idx = blockIdx.x * blockDim.x + threadIdx.x;
    if (idx < kHID * kHID) {
        int h = idx >> 10;
        int col = idx & 1023;
        int n = col >> 6, d = col & 63;
        out[idx] = W[((size_t)n * kHID + h) * kDK + d];
    }
}

// ---------------- fp32 -> bf16 hi/lo split (row-major, elementwise, x4) ----------------
__global__ void split4_kernel(const float* __restrict__ in,
                              __nv_bfloat16* __restrict__ hi,
                              __nv_bfloat16* __restrict__ lo, int n4) {
    int i = blockIdx.x * 256 + threadIdx.x;
    if (i >= n4) return;
    float4 x = ((const float4*)in)[i];
    __nv_bfloat16 h0 = __float2bfloat16(x.x), h1 = __float2bfloat16(x.y);
    __nv_bfloat16 h2 = __float2bfloat16(x.z), h3 = __float2bfloat16(x.w);
    __nv_bfloat16 l0 = __float2bfloat16(x.x - __bfloat162float(h0));
    __nv_bfloat16 l1 = __float2bfloat16(x.y - __bfloat162float(h1));
    __nv_bfloat16 l2 = __float2bfloat16(x.z - __bfloat162float(h2));
    __nv_bfloat16 l3 = __float2bfloat16(x.w - __bfloat162float(h3));
    __nv_bfloat162* hp = (__nv_bfloat162*)hi;
    __nv_bfloat162* lp = (__nv_bfloat162*)lo;
    hp[i*2+0] = __nv_bfloat162(h0, h1); hp[i*2+1] = __nv_bfloat162(h2, h3);
    lp[i*2+0] = __nv_bfloat162(l0, l1); lp[i*2+1] = __nv_bfloat162(l2, l3);
}

// ---------------- fp32 [K,N] -> bf16 hi/lo [N,K] (transpose + split) ----------------
// grid(N/32, K/32), block(32,8). K,N multiples of 32.
__global__ void splitT_kernel(const float* __restrict__ in,
                              __nv_bfloat16* __restrict__ hi,
                              __nv_bfloat16* __restrict__ lo, int K, int N) {
    __shared__ float t[32][33];
    int n0 = blockIdx.x * 32, k0 = blockIdx.y * 32;
    int tx = threadIdx.x;
#pragma unroll
    for (int i = threadIdx.y; i < 32; i += 8)
        t[i][tx] = in[(size_t)(k0 + i) * N + n0 + tx];
    __syncthreads();
#pragma unroll
    for (int i = threadIdx.y; i < 32; i += 8) {
        float x = t[tx][i];     // = in[k0+tx][n0+i]
        __nv_bfloat16 h = __float2bfloat16(x);
        size_t o = (size_t)(n0 + i) * K + k0 + tx;
        hi[o] = h;
        lo[o] = __float2bfloat16(x - __bfloat162float(h));
    }
}

// ---------------- bf16-split tensor-core GEMM ----------------
// C[M,N] = (Ahi+Alo)@(Bhi+Blo) approx (3 terms) + bias
// A layouts: [M,K] row-major bf16. B layouts: [N,K] (k-contiguous). N%128==0, K%32==0.
// EPI: 0 plain, 1 relu, 2 qkv-scatter.
template<int EPI>
__global__ __launch_bounds__(256)
void hgemm_kernel(const __nv_bfloat16* __restrict__ aHi, const __nv_bfloat16* __restrict__ aLo,
                  const __nv_bfloat16* __restrict__ bHi, const __nv_bfloat16* __restrict__ bLo,
                  const float* __restrict__ bias, float* __restrict__ C,
                  int M, int N, int K) {
    constexpr int PITCH = 40;   // bf16 elems per smem row (conflict-free fragment loads)
    __shared__ __align__(16) __nv_bfloat16 As[128 * PITCH];
    __shared__ __align__(16) __nv_bfloat16 Bs[128 * PITCH];
    int tid = threadIdx.x;
    int wid = tid >> 5, lane = tid & 31;
    int wm = wid >> 2, wn = wid & 3;         // 2 x 4 warps -> warp tile 64(m) x 32(n)
    int r = lane >> 2, c2 = (lane & 3) * 2;
    int m0 = blockIdx.y * 128, n0 = blockIdx.x * 128;

    float acc[4][4][4] = {};                  // [mi][ni][c0..c3]

#pragma unroll 1
    for (int term = 0; term < 3; term++) {
        const __nv_bfloat16* A = (term == 2) ? aLo : aHi;
        const __nv_bfloat16* B = (term == 1) ? bLo : bHi;
#pragma unroll 1
        for (int k0 = 0; k0 < K; k0 += 32) {
            __syncthreads();
#pragma unroll
            for (int i = 0; i < 2; i++) {
                int idx = tid + i * 256;         // 512 uint4 per tile
                int row = idx >> 2;
                int c4 = (idx & 3) * 8;          // k offset in elems
                uint4 va = make_uint4(0u, 0u, 0u, 0u);
                if (m0 + row < M)
                    va = *(const uint4*)&A[(size_t)(m0 + row) * K + k0 + c4];
                *(uint4*)&As[row * PITCH + c4] = va;
                uint4 vb = *(const uint4*)&B[(size_t)(n0 + row) * K + k0 + c4];
                *(uint4*)&Bs[row * PITCH + c4] = vb;
            }
            __syncthreads();
#pragma unroll
            for (int ks = 0; ks < 32; ks += 16) {
                uint32_t afr[4][4], bfr[4][2];
#pragma unroll
                for (int mi = 0; mi < 4; mi++) {
                    const __nv_bfloat16* p = &As[(wm * 64 + mi * 16 + r) * PITCH + ks + c2];
                    afr[mi][0] = *(const uint32_t*)p;
                    afr[mi][1] = *(const uint32_t*)(p + 8 * PITCH);
                    afr[mi][2] = *(const uint32_t*)(p + 8);
                    afr[mi][3] = *(const uint32_t*)(p + 8 * PITCH + 8);
                }
#pragma unroll
                for (int ni = 0; ni < 4; ni++) {
                    const __nv_bfloat16* p = &Bs[(wn * 32 + ni * 8 + r) * PITCH + ks + c2];
                    bfr[ni][0] = *(const uint32_t*)p;
                    bfr[ni][1] = *(const uint32_t*)(p + 8);
                }
#pragma unroll
                for (int mi = 0; mi < 4; mi++)
#pragma unroll
                    for (int ni = 0; ni < 4; ni++)
                        asm volatile(
                            "mma.sync.aligned.m16n8k16.row.col.f32.bf16.bf16.f32 "
                            "{%0,%1,%2,%3}, {%4,%5,%6,%7}, {%8,%9}, {%0,%1,%2,%3};"
                            : "+f"(acc[mi][ni][0]), "+f"(acc[mi][ni][1]),
                              "+f"(acc[mi][ni][2]), "+f"(acc[mi][ni][3])
                            : "r"(afr[mi][0]), "r"(afr[mi][1]),
                              "r"(afr[mi][2]), "r"(afr[mi][3]),
                              "r"(bfr[ni][0]), "r"(bfr[ni][1]));
            }
        }
    }

    // epilogue
#pragma unroll
    for (int mi = 0; mi < 4; mi++) {
#pragma unroll
        for (int half = 0; half < 2; half++) {
            int row = m0 + wm * 64 + mi * 16 + r + half * 8;
            if (row >= M) continue;
#pragma unroll
            for (int ni = 0; ni < 4; ni++) {
                int col = n0 + wn * 32 + ni * 8 + c2;
                float v0 = acc[mi][ni][half * 2 + 0] + bias[col];
                float v1 = acc[mi][ni][half * 2 + 1] + bias[col + 1];
                if (EPI == 1) { v0 = fmaxf(v0, 0.f); v1 = fmaxf(v1, 0.f); }
                if (EPI == 2) {
                    int b = row / kS, s = row % kS;
                    int n = col >> 6, d = col & 63;
                    size_t base = (((size_t)(b * kNH + n)) * kS + s) * kDK + d;
                    C[base] = v0; C[base + 1] = v1;
                } else {
                    *(float2*)&C[(size_t)row * N + col] = make_float2(v0, v1);
                }
            }
        }
    }
}

// ---------------- attention scores: w[s][t] = floor((k_s . q_t)/8), mask t>s ----------------
__global__ __launch_bounds__(256)
void scores_kernel() {
    int bh = blockIdx.z;
    int s0 = blockIdx.y * 64, t0 = blockIdx.x * 64;
    if (t0 > s0 + 63) return;   // tile fully masked (softmax writes zeros there)

    __shared__ float Ks[64][68];   // [d][s]
    __shared__ float Qs[64][68];   // [d][t]
    const float* kp = g_k + (size_t)bh * kS * kDK;
    const float* qp = g_q + (size_t)bh * kS * kDK;
    int tid = threadIdx.x;
#pragma unroll
    for (int i = 0; i < 4; i++) {
        int idx = tid + i * 256;            // 1024 float4
        int r = idx >> 4;                   // 0..63
        int c = (idx & 15) << 2;            // 0..60
        float4 vk = (s0 + r < kS) ? *(const float4*)&kp[(size_t)(s0 + r) * kDK + c]
                                  : make_float4(0.f, 0.f, 0.f, 0.f);
        float4 vq = (t0 + r < kS) ? *(const float4*)&qp[(size_t)(t0 + r) * kDK + c]
                                  : make_float4(0.f, 0.f, 0.f, 0.f);
        Ks[c + 0][r] = vk.x; Ks[c + 1][r] = vk.y; Ks[c + 2][r] = vk.z; Ks[c + 3][r] = vk.w;
        Qs[c + 0][r] = vq.x; Qs[c + 1][r] = vq.y; Qs[c + 2][r] = vq.z; Qs[c + 3][r] = vq.w;
    }
    __syncthreads();

    int tr = tid >> 4, tc = tid & 15;
    float acc[4][4] = {};
#pragma unroll
    for (int d = 0; d < 64; d++) {
        float ra[4], rb[4];
#pragma unroll
        for (int i = 0; i < 4; i++) ra[i] = Ks[d][tr * 4 + i];
#pragma unroll
        for (int j = 0; j < 4; j++) rb[j] = Qs[d][tc * 4 + j];
#pragma unroll
        for (int i = 0; i < 4; i++)
#pragma unroll
            for (int j = 0; j < 4; j++) acc[i][j] += ra[i] * rb[j];
    }
#pragma unroll
    for (int i = 0; i < 4; i++) {
        int s = s0 + tr * 4 + i;
        if (s >= kS) continue;
#pragma unroll
        for (int j = 0; j < 4; j++) {
            int t = t0 + tc * 4 + j;
            if (t >= kS) continue;
            float w = (t > s) ? __int_as_float(0xff800000)
                              : floorf(acc[i][j] * 0.125f);
            g_scores[((size_t)bh * kS + s) * kS + t] = w;
        }
    }
}

// ---------------- row softmax over t <= s; zeros for t > s ----------------
__global__ __launch_bounds__(256)
void softmax_kernel() {
    int r = blockIdx.x;                 // bh*S + s
    int s = r % kS;
    float* row = g_scores + (size_t)r * kS;
    int tid = threadIdx.x;
    __shared__ float red[256];

    float m = -1e30f;
    for (int t = tid; t <= s; t += 256) m = fmaxf(m, row[t]);
    red[tid] = m; __syncthreads();
    for (int o = 128; o; o >>= 1) { if (tid < o) red[tid] = fmaxf(red[tid], red[tid + o]); __syncthreads(); }
    m = red[0]; __syncthreads();

    float ls = 0.f;
    for (int t = tid; t <= s; t += 256) {
        float e = expf(row[t] - m);
        row[t] = e;
        ls += e;
    }
    red[tid] = ls; __syncthreads();
    for (int o = 128; o; o >>= 1) { if (tid < o) red[tid] += red[tid + o]; __syncthreads(); }
    float inv = 1.f / red[0];
    __syncthreads();

    for (int t = tid; t < kS; t += 256) row[t] = (t <= s) ? row[t] * inv : 0.f;
}

// ---------------- attn = score @ V, scattered to concat-head layout ----------------
__global__ __launch_bounds__(256)
void pv_kernel() {
    int bh = blockIdx.y;
    int s0 = blockIdx.x * 64;
    const float* sc = g_scores + (size_t)bh * kS * kS;
    const float* vp = g_v + (size_t)bh * kS * kDK;
    __shared__ float Ss[32][68];
    __shared__ float Vs[32][68];
    int tid = threadIdx.x;
    int tr = tid >> 4, tc = tid & 15;
    float acc[4][4] = {};
    int kend = min(kS, s0 + 64);

    for (int t0 = 0; t0 < kend; t0 += 32) {
#pragma unroll
        for (int i = 0; i < 2; i++) {
            int idx = tid + i * 256;
            int r = idx >> 3;
            int c = (idx & 7) << 2;
            int s = s0 + r, t = t0 + c;
            float4 vv = (s < kS && t < kS)
                ? *(const float4*)&sc[(size_t)s * kS + t]
                : make_float4(0.f, 0.f, 0.f, 0.f);
            Ss[c + 0][r] = vv.x; Ss[c + 1][r] = vv.y; Ss[c + 2][r] = vv.z; Ss[c + 3][r] = vv.w;

            int vr = idx >> 4;
            int vc = (idx & 15) << 2;
            float4 vv2 = (t0 + vr < kS)
                ? *(const float4*)&vp[(size_t)(t0 + vr) * kDK + vc]
                : make_float4(0.f, 0.f, 0.f, 0.f);
            *(float4*)&Vs[vr][vc] = vv2;
        }
        __syncthreads();
#pragma unroll
        for (int k = 0; k < 32; k++) {
            float ra[4], rb[4];
#pragma unroll
            for (int i = 0; i < 4; i++) ra[i] = Ss[k][tr * 4 + i];
#pragma unroll
            for (int j = 0; j < 4; j++) rb[j] = Vs[k][tc * 4 + j];
#pragma unroll
            for (int i = 0; i < 4; i++)
#pragma unroll
                for (int j = 0; j < 4; j++) acc[i][j] += ra[i] * rb[j];
        }
        __syncthreads();
    }

    int b = bh >> 4, n = bh & 15;
#pragma unroll
    for (int i = 0; i < 4; i++) {
        int s = s0 + tr * 4 + i;
        if (s >= kS) continue;
#pragma unroll
        for (int j = 0; j < 4; j++) {
            g_attn[((size_t)(b * kS + s)) * kHID + n * kDK + tc * 4 + j] = acc[i][j];
        }
    }
}

// ---------------- out = LayerNorm(x + delta) * g + b ----------------
__global__ __launch_bounds__(256)
void add_ln_kernel(const float* __restrict__ xin, const float* __restrict__ dl,
                   const float* __restrict__ g, const float* __restrict__ b,
                   float* __restrict__ out) {
    int row = blockIdx.x;
    int tid = threadIdx.x;
    const float* xr = xin + (size_t)row * kHID;
    const float* dr = dl  + (size_t)row * kHID;
    __shared__ float red[256];

    float v[4]; float ls = 0.f;
#pragma unroll
    for (int i = 0; i < 4; i++) { int c = tid + i * 256; v[i] = xr[c] + dr[c]; ls += v[i]; }
    red[tid] = ls; __syncthreads();
    for (int o = 128; o; o >>= 1) { if (tid < o) red[tid] += red[tid + o]; __syncthreads(); }
    float mu = red[0] * (1.f / kHID);
    __syncthreads();

    float lv = 0.f;
#pragma unroll
    for (int i = 0; i < 4; i++) { float d = v[i] - mu; lv += d * d; }
    red[tid] = lv; __syncthreads();
    for (int o = 128; o; o >>= 1) { if (tid < o) red[tid] += red[tid + o]; __syncthreads(); }
    float rstd = 1.f / sqrtf(red[0] * (1.f / kHID) + 1e-5f);

    float* orow = out + (size_t)row * kHID;
#pragma unroll
    for (int i = 0; i < 4; i++) {
        int c = tid + i * 256;
        orow[c] = (v[i] - mu) * rstd * g[c] + b[c];
    }
}

// ---------------- launcher ----------------
extern "C" void kernel_launch(void* const* d_in, const int* in_sizes, int n_in,
                              void* d_out, int out_size) {
    const int*   tok  = (const int*)  d_in[0];
    const float* emb  = (const float*)d_in[1];
    const float* Wq   = (const float*)d_in[2];
    const float* bq   = (const float*)d_in[3];
    const float* Wk   = (const float*)d_in[4];
    const float* bk   = (const float*)d_in[5];
    const float* Wv   = (const float*)d_in[6];
    const float* bv   = (const float*)d_in[7];
    const float* Wc   = (const float*)d_in[8];
    const float* bc   = (const float*)d_in[9];
    const float* ln1g = (const float*)d_in[10];
    const float* ln1b = (const float*)d_in[11];
    const float* W1   = (const float*)d_in[12];
    const float* b1   = (const float*)d_in[13];
    const float* W2   = (const float*)d_in[14];
    const float* b2   = (const float*)d_in[15];
    const float* ln2g = (const float*)d_in[16];
    const float* ln2b = (const float*)d_in[17];
    const float* Wlog = (const float*)d_in[18];
    const float* blog = (const float*)d_in[19];
    float* out = (float*)d_out;

    float *px, *pq, *pk, *pv, *pattn, *px1, *ph, *pff, *px2, *pwq, *pwk, *pwv, *pscores;
    cudaGetSymbolAddress((void**)&px,     g_x);
    cudaGetSymbolAddress((void**)&pq,     g_q);
    cudaGetSymbolAddress((void**)&pk,     g_k);
    cudaGetSymbolAddress((void**)&pv,     g_v);
    cudaGetSymbolAddress((void**)&pattn,  g_attn);
    cudaGetSymbolAddress((void**)&px1,    g_x1);
    cudaGetSymbolAddress((void**)&ph,     g_h);
    cudaGetSymbolAddress((void**)&pff,    g_ff);
    cudaGetSymbolAddress((void**)&px2,    g_x2);
    cudaGetSymbolAddress((void**)&pwq,    g_wq);
    cudaGetSymbolAddress((void**)&pwk,    g_wk);
    cudaGetSymbolAddress((void**)&pwv,    g_wv);
    cudaGetSymbolAddress((void**)&pscores,g_scores);

    // split buffers alias the scores pool (time-disjoint with score usage)
    __nv_bfloat16* pbhi = (__nv_bfloat16*)((char*)pscores + kOffBhi);
    __nv_bfloat16* pblo = (__nv_bfloat16*)((char*)pscores + kOffBlo);
    __nv_bfloat16* pahi = (__nv_bfloat16*)((char*)pscores + kOffAhi);
    __nv_bfloat16* palo = (__nv_bfloat16*)((char*)pscores + kOffAlo);

    dim3 t328(32, 8);

    // 1. positional encoding + embedding
    pe_kernel<<<1, 1024>>>();
    embed_kernel<<<kROWS, 256>>>(tok, emb);

    // 2. repack per-head QKV weights into [HID, HID] fp32
    pack_w_kernel<<<(kHID * kHID + 255) / 256, 256>>>(Wq, pwq);
    pack_w_kernel<<<(kHID * kHID + 255) / 256, 256>>>(Wk, pwk);
    pack_w_kernel<<<(kHID * kHID + 255) / 256, 256>>>(Wv, pwv);

    // 3. QKV projections on tensor cores (hi/lo split), scatter epilogue
    //    (scores region holds split data here; scores not yet written)
    split4_kernel<<<(kROWS * kHID / 4 + 255) / 256, 256>>>(px, pahi, palo, kROWS * kHID / 4);
    dim3 gQ(kHID / 128, (kROWS + 127) / 128);
    splitT_kernel<<<dim3(kHID / 32, kHID / 32), t328>>>(pwq, pbhi, pblo, kHID, kHID);
    hgemm_kernel<2><<<gQ, 256>>>(pahi, palo, pbhi, pblo, bq, pq, kROWS, kHID, kHID);
    splitT_kernel<<<dim3(kHID / 32, kHID / 32), t328>>>(pwk, pbhi, pblo, kHID, kHID);
    hgemm_kernel<2><<<gQ, 256>>>(pahi, palo, pbhi, pblo, bk, pk, kROWS, kHID, kHID);
    splitT_kernel<<<dim3(kHID / 32, kHID / 32), t328>>>(pwv, pbhi, pblo, kHID, kHID);
    hgemm_kernel<2><<<gQ, 256>>>(pahi, palo, pbhi, pblo, bv, pv, kROWS, kHID, kHID);

    // 4. attention (fp32; scores OVERWRITE the split buffers — they are dead here)
    scores_kernel<<<dim3(16, 16, kBH), 256>>>();
    softmax_kernel<<<kBH * kS, 256>>>();
    pv_kernel<<<dim3(16, kBH), 256>>>();

    // 5. output projection + residual + LN1 (splits overwrite scores — dead after pv)
    split4_kernel<<<(kROWS * kHID / 4 + 255) / 256, 256>>>(pattn, pahi, palo, kROWS * kHID / 4);
    splitT_kernel<<<dim3(kHID / 32, kHID / 32), t328>>>(Wc, pbhi, pblo, kHID, kHID);
    hgemm_kernel<0><<<dim3(kHID / 128, (kROWS + 127) / 128), 256>>>(pahi, palo, pbhi, pblo, bc, pff, kROWS, kHID, kHID);
    add_ln_kernel<<<kROWS, 256>>>(px, pff, ln1g, ln1b, px1);

    // 6. feed-forward + residual + LN2
    split4_kernel<<<(kROWS * kHID / 4 + 255) / 256, 256>>>(px1, pahi, palo, kROWS * kHID / 4);
    splitT_kernel<<<dim3(kFFH / 32, kHID / 32), t328>>>(W1, pbhi, pblo, kHID, kFFH);
    hgemm_kernel<1><<<dim3(kFFH / 128, (kROWS + 127) / 128), 256>>>(pahi, palo, pbhi, pblo, b1, ph, kROWS, kFFH, kHID);
    split4_kernel<<<(kROWS * kFFH / 4 + 255) / 256, 256>>>(ph, pahi, palo, kROWS * kFFH / 4);
    splitT_kernel<<<dim3(kHID / 32, kFFH / 32), t328>>>(W2, pbhi, pblo, kFFH, kHID);
    hgemm_kernel<0><<<dim3(kHID / 128, (kROWS + 127) / 128), 256>>>(pahi, palo, pbhi, pblo, b2, pff, kROWS, kHID, kFFH);
    add_ln_kernel<<<kROWS, 256>>>(px1, pff, ln2g, ln2b, px2);

    // 7. logits (dominant GEMM) on tensor cores -> d_out
    split4_kernel<<<(kROWS * kHID / 4 + 255) / 256, 256>>>(px2, pahi, palo, kROWS * kHID / 4);
    splitT_kernel<<<dim3(kVOC / 32, kHID / 32), t328>>>(Wlog, pbhi, pblo, kHID, kVOC);
    hgemm_kernel<0><<<dim3(kVOC / 128, (kROWS + 127) / 128), 256>>>(pahi, palo, pbhi, pblo, blog, out, kROWS, kVOC, kHID);

    (void)in_sizes; (void)n_in; (void)out_size;
}

// round 6
// speedup vs baseline: 2.2999x; 1.3125x over previous
#include <cuda_runtime.h>
#include <cuda_bf16.h>
#include <math.h>
#include <stdint.h>

// ---------------- problem constants ----------------
constexpr int kB    = 4;
constexpr int kS    = 1000;
constexpr int kHID  = 1024;
constexpr int kNH   = 16;
constexpr int kDK   = 64;
constexpr int kFFH  = 2048;
constexpr int kVOC  = 32000;
constexpr int kROWS = kB * kS;     // 4000
constexpr int kBH   = kB * kNH;    // 64

// ---------------- device scratch (no allocations allowed) ----------------
// bf16 split buffers ALIAS g_scores (time-disjoint usage; see launcher).
__device__ float g_pe[kHID];
__device__ float g_x   [kROWS * kHID];
__device__ float g_q   [kBH * kS * kDK];
__device__ float g_k   [kBH * kS * kDK];
__device__ float g_v   [kBH * kS * kDK];
__device__ __align__(256) float g_scores[(size_t)kBH * kS * kS];   // 256 MB (also hosts split buffers)
__device__ float g_attn[kROWS * kHID];
__device__ float g_x1  [kROWS * kHID];
__device__ float g_h   [kROWS * kFFH];
__device__ float g_ff  [kROWS * kHID];
__device__ float g_x2  [kROWS * kHID];
__device__ float g_wq  [kHID * kHID];
__device__ float g_wk  [kHID * kHID];
__device__ float g_wv  [kHID * kHID];

// byte offsets of split buffers inside g_scores (all 16B-aligned)
constexpr size_t kOffBhi = 0;
constexpr size_t kOffBlo = (size_t)kHID * kVOC * 2;
constexpr size_t kOffAhi = kOffBlo + (size_t)kHID * kVOC * 2;
constexpr size_t kOffAlo = kOffAhi + (size_t)kROWS * kFFH * 2;
static_assert(kOffAlo + (size_t)kROWS * kFFH * 2 <= (size_t)kBH * kS * kS * 4, "pool overflow");

// ---------------- positional encoding (source-bug constant vector) ----------------
__global__ void pe_kernel() {
    int c = threadIdx.x;                     // 0..1023
    int i = c & ~1;                          // even index
    double tmp = 999.0 * exp(-(double)i / 1024.0 * log(10000.0));
    g_pe[c] = (c & 1) ? (float)cos(tmp) : (float)sin(tmp);
}

// x[row] = emb[token[row]] + pe
__global__ void embed_kernel(const int* __restrict__ tok, const float* __restrict__ emb) {
    int row = blockIdx.x;
    int t = tok[row];
    const float4* e = (const float4*)(emb + (size_t)t * kHID);
    const float4* p = (const float4*)g_pe;
    float4* xo = (float4*)(g_x + (size_t)row * kHID);
    int c = threadIdx.x;
    float4 a = e[c], b = p[c];
    xo[c] = make_float4(a.x + b.x, a.y + b.y, a.z + b.z, a.w + b.w);
}

// repack W[n][h][d] -> Wp[h][n*64+d]
__global__ void pack_w_kernel(const float* __restrict__ W, float* __restrict__ out) {
    int idx = blockIdx.x * blockDim.x + threadIdx.x;
    if (idx < kHID * kHID) {
        int h = idx >> 10;
        int col = idx & 1023;
        int n = col >> 6, d = col & 63;
        out[idx] = W[((size_t)n * kHID + h) * kDK + d];
    }
}

// ---------------- fp32 -> bf16 hi/lo split (row-major, elementwise, x4) ----------------
__global__ void split4_kernel(const float* __restrict__ in,
                              __nv_bfloat16* __restrict__ hi,
                              __nv_bfloat16* __restrict__ lo, int n4) {
    int i = blockIdx.x * 256 + threadIdx.x;
    if (i >= n4) return;
    float4 x = ((const float4*)in)[i];
    __nv_bfloat16 h0 = __float2bfloat16(x.x), h1 = __float2bfloat16(x.y);
    __nv_bfloat16 h2 = __float2bfloat16(x.z), h3 = __float2bfloat16(x.w);
    __nv_bfloat16 l0 = __float2bfloat16(x.x - __bfloat162float(h0));
    __nv_bfloat16 l1 = __float2bfloat16(x.y - __bfloat162float(h1));
    __nv_bfloat16 l2 = __float2bfloat16(x.z - __bfloat162float(h2));
    __nv_bfloat16 l3 = __float2bfloat16(x.w - __bfloat162float(h3));
    __nv_bfloat162* hp = (__nv_bfloat162*)hi;
    __nv_bfloat162* lp = (__nv_bfloat162*)lo;
    hp[i*2+0] = __nv_bfloat162(h0, h1); hp[i*2+1] = __nv_bfloat162(h2, h3);
    lp[i*2+0] = __nv_bfloat162(l0, l1); lp[i*2+1] = __nv_bfloat162(l2, l3);
}

// ---------------- fp32 [K,N] -> bf16 hi/lo [N,K] (transpose + split) ----------------
__global__ void splitT_kernel(const float* __restrict__ in,
                              __nv_bfloat16* __restrict__ hi,
                              __nv_bfloat16* __restrict__ lo, int K, int N) {
    __shared__ float t[32][33];
    int n0 = blockIdx.x * 32, k0 = blockIdx.y * 32;
    int tx = threadIdx.x;
#pragma unroll
    for (int i = threadIdx.y; i < 32; i += 8)
        t[i][tx] = in[(size_t)(k0 + i) * N + n0 + tx];
    __syncthreads();
#pragma unroll
    for (int i = threadIdx.y; i < 32; i += 8) {
        float x = t[tx][i];
        __nv_bfloat16 h = __float2bfloat16(x);
        size_t o = (size_t)(n0 + i) * K + k0 + tx;
        hi[o] = h;
        lo[o] = __float2bfloat16(x - __bfloat162float(h));
    }
}

// ---------------- cp.async helpers ----------------
__device__ __forceinline__ void cp16(uint32_t dst, const void* src, bool full) {
    int sz = full ? 16 : 0;
    asm volatile("cp.async.cg.shared.global [%0], [%1], 16, %2;"
                 :: "r"(dst), "l"(src), "r"(sz) : "memory");
}
__device__ __forceinline__ void cp_commit() {
    asm volatile("cp.async.commit_group;" ::: "memory");
}

// ---------------- fused bf16-split tensor-core GEMM (single K pass, 3 MMAs/tile) ----------------
// C = Ahi@Bhi + Ahi@Blo + Alo@Bhi + bias.  A:[M,K] row-major, B:[N,K] k-contig.
// 128x128 tile, BK=32, 256 threads, 2-stage cp.async pipeline.
// Dynamic smem: 2 stages x 4 arrays x 128 x PITCH(40) bf16 = 81920 B.
constexpr int kPITCH = 40;
constexpr int kArrSz = 128 * kPITCH;          // elems per array
constexpr int kGemmSmem = 2 * 4 * kArrSz * 2; // bytes

template<int EPI>
__global__ __launch_bounds__(256)
void hgemm_fused(const __nv_bfloat16* __restrict__ aHi, const __nv_bfloat16* __restrict__ aLo,
                 const __nv_bfloat16* __restrict__ bHi, const __nv_bfloat16* __restrict__ bLo,
                 const float* __restrict__ bias, float* __restrict__ C,
                 int M, int N, int K) {
    extern __shared__ __align__(16) __nv_bfloat16 dynsm[];
    uint32_t smbase;
    { uint64_t t64; asm("cvta.to.shared.u64 %0, %1;" : "=l"(t64) : "l"(dynsm)); smbase = (uint32_t)t64; }

    int tid = threadIdx.x;
    int wid = tid >> 5, lane = tid & 31;
    int wm = wid >> 2, wn = wid & 3;          // 2x4 warps -> warp tile 64(m) x 32(n)
    int r = lane >> 2, c2 = (lane & 3) * 2;
    int m0 = blockIdx.y * 128, n0 = blockIdx.x * 128;

    const __nv_bfloat16* gsrc[4] = {aHi, aLo, bHi, bLo};

    auto issue_tile = [&](int stage, int k0) {
#pragma unroll
        for (int arr = 0; arr < 4; arr++) {
            const __nv_bfloat16* gp = gsrc[arr];
            bool isA = arr < 2;
#pragma unroll
            for (int i = 0; i < 2; i++) {
                int idx = tid + i * 256;          // 512 16B-chunks per array
                int row = idx >> 2;
                int c4 = (idx & 3) * 8;
                int grow = (isA ? m0 : n0) + row;
                bool ok = isA ? (grow < M) : true;
                const void* src = gp + (size_t)(ok ? grow : 0) * K + k0 + c4;
                uint32_t dst = smbase + (uint32_t)(((stage * 4 + arr) * kArrSz + row * kPITCH + c4) * 2);
                cp16(dst, src, ok);
            }
        }
    };

    float acc[4][4][4] = {};                   // [mi][ni][c]

    issue_tile(0, 0);
    cp_commit();

    int stage = 0;
    for (int k0 = 0; k0 < K; k0 += 32) {
        bool hasNext = (k0 + 32) < K;
        if (hasNext) {
            issue_tile(stage ^ 1, k0 + 32);
            cp_commit();
            asm volatile("cp.async.wait_group 1;" ::: "memory");
        } else {
            asm volatile("cp.async.wait_group 0;" ::: "memory");
        }
        __syncthreads();

        const __nv_bfloat16* sAhi = dynsm + (stage * 4 + 0) * kArrSz;
        const __nv_bfloat16* sAlo = dynsm + (stage * 4 + 1) * kArrSz;
        const __nv_bfloat16* sBhi = dynsm + (stage * 4 + 2) * kArrSz;
        const __nv_bfloat16* sBlo = dynsm + (stage * 4 + 3) * kArrSz;

#pragma unroll
        for (int ks = 0; ks < 32; ks += 16) {
            uint32_t ahi[4][4], alo[4][4], bhi[4][2], blo[4][2];
#pragma unroll
            for (int mi = 0; mi < 4; mi++) {
                int rr = (wm * 64 + mi * 16 + r) * kPITCH + ks + c2;
                ahi[mi][0] = *(const uint32_t*)&sAhi[rr];
                ahi[mi][1] = *(const uint32_t*)&sAhi[rr + 8 * kPITCH];
                ahi[mi][2] = *(const uint32_t*)&sAhi[rr + 8];
                ahi[mi][3] = *(const uint32_t*)&sAhi[rr + 8 * kPITCH + 8];
                alo[mi][0] = *(const uint32_t*)&sAlo[rr];
                alo[mi][1] = *(const uint32_t*)&sAlo[rr + 8 * kPITCH];
                alo[mi][2] = *(const uint32_t*)&sAlo[rr + 8];
                alo[mi][3] = *(const uint32_t*)&sAlo[rr + 8 * kPITCH + 8];
            }
#pragma unroll
            for (int ni = 0; ni < 4; ni++) {
                int rr = (wn * 32 + ni * 8 + r) * kPITCH + ks + c2;
                bhi[ni][0] = *(const uint32_t*)&sBhi[rr];
                bhi[ni][1] = *(const uint32_t*)&sBhi[rr + 8];
                blo[ni][0] = *(const uint32_t*)&sBlo[rr];
                blo[ni][1] = *(const uint32_t*)&sBlo[rr + 8];
            }
#define MMA(A0,A1,A2,A3,B0,B1,ACC) \
    asm volatile("mma.sync.aligned.m16n8k16.row.col.f32.bf16.bf16.f32 " \
                 "{%0,%1,%2,%3}, {%4,%5,%6,%7}, {%8,%9}, {%0,%1,%2,%3};" \
                 : "+f"(ACC[0]), "+f"(ACC[1]), "+f"(ACC[2]), "+f"(ACC[3]) \
                 : "r"(A0), "r"(A1), "r"(A2), "r"(A3), "r"(B0), "r"(B1))
#pragma unroll
            for (int mi = 0; mi < 4; mi++)
#pragma unroll
                for (int ni = 0; ni < 4; ni++) {
                    MMA(ahi[mi][0], ahi[mi][1], ahi[mi][2], ahi[mi][3],
                        bhi[ni][0], bhi[ni][1], acc[mi][ni]);
                    MMA(ahi[mi][0], ahi[mi][1], ahi[mi][2], ahi[mi][3],
                        blo[ni][0], blo[ni][1], acc[mi][ni]);
                    MMA(alo[mi][0], alo[mi][1], alo[mi][2], alo[mi][3],
                        bhi[ni][0], bhi[ni][1], acc[mi][ni]);
                }
#undef MMA
        }
        __syncthreads();
        stage ^= 1;
    }

    // epilogue
#pragma unroll
    for (int mi = 0; mi < 4; mi++) {
#pragma unroll
        for (int half = 0; half < 2; half++) {
            int row = m0 + wm * 64 + mi * 16 + r + half * 8;
            if (row >= M) continue;
#pragma unroll
            for (int ni = 0; ni < 4; ni++) {
                int col = n0 + wn * 32 + ni * 8 + c2;
                float v0 = acc[mi][ni][half * 2 + 0] + bias[col];
                float v1 = acc[mi][ni][half * 2 + 1] + bias[col + 1];
                if (EPI == 1) { v0 = fmaxf(v0, 0.f); v1 = fmaxf(v1, 0.f); }
                if (EPI == 2) {
                    int b = row / kS, s = row % kS;
                    int n = col >> 6, d = col & 63;
                    size_t base = (((size_t)(b * kNH + n)) * kS + s) * kDK + d;
                    C[base] = v0; C[base + 1] = v1;
                } else {
                    *(float2*)&C[(size_t)row * N + col] = make_float2(v0, v1);
                }
            }
        }
    }
}

// ---------------- attention scores: w[s][t] = floor((k_s . q_t)/8), mask t>s ----------------
__global__ __launch_bounds__(256)
void scores_kernel() {
    int bh = blockIdx.z;
    int s0 = blockIdx.y * 64, t0 = blockIdx.x * 64;
    if (t0 > s0 + 63) return;

    __shared__ float Ks[64][68];
    __shared__ float Qs[64][68];
    const float* kp = g_k + (size_t)bh * kS * kDK;
    const float* qp = g_q + (size_t)bh * kS * kDK;
    int tid = threadIdx.x;
#pragma unroll
    for (int i = 0; i < 4; i++) {
        int idx = tid + i * 256;
        int r = idx >> 4;
        int c = (idx & 15) << 2;
        float4 vk = (s0 + r < kS) ? *(const float4*)&kp[(size_t)(s0 + r) * kDK + c]
                                  : make_float4(0.f, 0.f, 0.f, 0.f);
        float4 vq = (t0 + r < kS) ? *(const float4*)&qp[(size_t)(t0 + r) * kDK + c]
                                  : make_float4(0.f, 0.f, 0.f, 0.f);
        Ks[c + 0][r] = vk.x; Ks[c + 1][r] = vk.y; Ks[c + 2][r] = vk.z; Ks[c + 3][r] = vk.w;
        Qs[c + 0][r] = vq.x; Qs[c + 1][r] = vq.y; Qs[c + 2][r] = vq.z; Qs[c + 3][r] = vq.w;
    }
    __syncthreads();

    int tr = tid >> 4, tc = tid & 15;
    float acc[4][4] = {};
#pragma unroll
    for (int d = 0; d < 64; d++) {
        float ra[4], rb[4];
#pragma unroll
        for (int i = 0; i < 4; i++) ra[i] = Ks[d][tr * 4 + i];
#pragma unroll
        for (int j = 0; j < 4; j++) rb[j] = Qs[d][tc * 4 + j];
#pragma unroll
        for (int i = 0; i < 4; i++)
#pragma unroll
            for (int j = 0; j < 4; j++) acc[i][j] += ra[i] * rb[j];
    }
#pragma unroll
    for (int i = 0; i < 4; i++) {
        int s = s0 + tr * 4 + i;
        if (s >= kS) continue;
#pragma unroll
        for (int j = 0; j < 4; j++) {
            int t = t0 + tc * 4 + j;
            if (t >= kS) continue;
            float w = (t > s) ? __int_as_float(0xff800000)
                              : floorf(acc[i][j] * 0.125f);
            g_scores[((size_t)bh * kS + s) * kS + t] = w;
        }
    }
}

// ---------------- row softmax over t <= s; zeros for t > s ----------------
__global__ __launch_bounds__(256)
void softmax_kernel() {
    int r = blockIdx.x;
    int s = r % kS;
    float* row = g_scores + (size_t)r * kS;
    int tid = threadIdx.x;
    __shared__ float red[256];

    float m = -1e30f;
    for (int t = tid; t <= s; t += 256) m = fmaxf(m, row[t]);
    red[tid] = m; __syncthreads();
    for (int o = 128; o; o >>= 1) { if (tid < o) red[tid] = fmaxf(red[tid], red[tid + o]); __syncthreads(); }
    m = red[0]; __syncthreads();

    float ls = 0.f;
    for (int t = tid; t <= s; t += 256) {
        float e = expf(row[t] - m);
        row[t] = e;
        ls += e;
    }
    red[tid] = ls; __syncthreads();
    for (int o = 128; o; o >>= 1) { if (tid < o) red[tid] += red[tid + o]; __syncthreads(); }
    float inv = 1.f / red[0];
    __syncthreads();

    for (int t = tid; t < kS; t += 256) row[t] = (t <= s) ? row[t] * inv : 0.f;
}

// ---------------- attn = score @ V, scattered to concat-head layout ----------------
__global__ __launch_bounds__(256)
void pv_kernel() {
    int bh = blockIdx.y;
    int s0 = blockIdx.x * 64;
    const float* sc = g_scores + (size_t)bh * kS * kS;
    const float* vp = g_v + (size_t)bh * kS * kDK;
    __shared__ float Ss[32][68];
    __shared__ float Vs[32][68];
    int tid = threadIdx.x;
    int tr = tid >> 4, tc = tid & 15;
    float acc[4][4] = {};
    int kend = min(kS, s0 + 64);

    for (int t0 = 0; t0 < kend; t0 += 32) {
#pragma unroll
        for (int i = 0; i < 2; i++) {
            int idx = tid + i * 256;
            int r = idx >> 3;
            int c = (idx & 7) << 2;
            int s = s0 + r, t = t0 + c;
            float4 vv = (s < kS && t < kS)
                ? *(const float4*)&sc[(size_t)s * kS + t]
                : make_float4(0.f, 0.f, 0.f, 0.f);
            Ss[c + 0][r] = vv.x; Ss[c + 1][r] = vv.y; Ss[c + 2][r] = vv.z; Ss[c + 3][r] = vv.w;

            int vr = idx >> 4;
            int vc = (idx & 15) << 2;
            float4 vv2 = (t0 + vr < kS)
                ? *(const float4*)&vp[(size_t)(t0 + vr) * kDK + vc]
                : make_float4(0.f, 0.f, 0.f, 0.f);
            *(float4*)&Vs[vr][vc] = vv2;
        }
        __syncthreads();
#pragma unroll
        for (int k = 0; k < 32; k++) {
            float ra[4], rb[4];
#pragma unroll
            for (int i = 0; i < 4; i++) ra[i] = Ss[k][tr * 4 + i];
#pragma unroll
            for (int j = 0; j < 4; j++) rb[j] = Vs[k][tc * 4 + j];
#pragma unroll
            for (int i = 0; i < 4; i++)
#pragma unroll
                for (int j = 0; j < 4; j++) acc[i][j] += ra[i] * rb[j];
        }
        __syncthreads();
    }

    int b = bh >> 4, n = bh & 15;
#pragma unroll
    for (int i = 0; i < 4; i++) {
        int s = s0 + tr * 4 + i;
        if (s >= kS) continue;
#pragma unroll
        for (int j = 0; j < 4; j++) {
            g_attn[((size_t)(b * kS + s)) * kHID + n * kDK + tc * 4 + j] = acc[i][j];
        }
    }
}

// ---------------- out = LayerNorm(x + delta) * g + b ----------------
__global__ __launch_bounds__(256)
void add_ln_kernel(const float* __restrict__ xin, const float* __restrict__ dl,
                   const float* __restrict__ g, const float* __restrict__ b,
                   float* __restrict__ out) {
    int row = blockIdx.x;
    int tid = threadIdx.x;
    const float* xr = xin + (size_t)row * kHID;
    const float* dr = dl  + (size_t)row * kHID;
    __shared__ float red[256];

    float v[4]; float ls = 0.f;
#pragma unroll
    for (int i = 0; i < 4; i++) { int c = tid + i * 256; v[i] = xr[c] + dr[c]; ls += v[i]; }
    red[tid] = ls; __syncthreads();
    for (int o = 128; o; o >>= 1) { if (tid < o) red[tid] += red[tid + o]; __syncthreads(); }
    float mu = red[0] * (1.f / kHID);
    __syncthreads();

    float lv = 0.f;
#pragma unroll
    for (int i = 0; i < 4; i++) { float d = v[i] - mu; lv += d * d; }
    red[tid] = lv; __syncthreads();
    for (int o = 128; o; o >>= 1) { if (tid < o) red[tid] += red[tid + o]; __syncthreads(); }
    float rstd = 1.f / sqrtf(red[0] * (1.f / kHID) + 1e-5f);

    float* orow = out + (size_t)row * kHID;
#pragma unroll
    for (int i = 0; i < 4; i++) {
        int c = tid + i * 256;
        orow[c] = (v[i] - mu) * rstd * g[c] + b[c];
    }
}

// ---------------- launcher ----------------
extern "C" void kernel_launch(void* const* d_in, const int* in_sizes, int n_in,
                              void* d_out, int out_size) {
    const int*   tok  = (const int*)  d_in[0];
    const float* emb  = (const float*)d_in[1];
    const float* Wq   = (const float*)d_in[2];
    const float* bq   = (const float*)d_in[3];
    const float* Wk   = (const float*)d_in[4];
    const float* bk   = (const float*)d_in[5];
    const float* Wv   = (const float*)d_in[6];
    const float* bv   = (const float*)d_in[7];
    const float* Wc   = (const float*)d_in[8];
    const float* bc   = (const float*)d_in[9];
    const float* ln1g = (const float*)d_in[10];
    const float* ln1b = (const float*)d_in[11];
    const float* W1   = (const float*)d_in[12];
    const float* b1   = (const float*)d_in[13];
    const float* W2   = (const float*)d_in[14];
    const float* b2   = (const float*)d_in[15];
    const float* ln2g = (const float*)d_in[16];
    const float* ln2b = (const float*)d_in[17];
    const float* Wlog = (const float*)d_in[18];
    const float* blog = (const float*)d_in[19];
    float* out = (float*)d_out;

    float *px, *pq, *pk, *pv, *pattn, *px1, *ph, *pff, *px2, *pwq, *pwk, *pwv, *pscores;
    cudaGetSymbolAddress((void**)&px,     g_x);
    cudaGetSymbolAddress((void**)&pq,     g_q);
    cudaGetSymbolAddress((void**)&pk,     g_k);
    cudaGetSymbolAddress((void**)&pv,     g_v);
    cudaGetSymbolAddress((void**)&pattn,  g_attn);
    cudaGetSymbolAddress((void**)&px1,    g_x1);
    cudaGetSymbolAddress((void**)&ph,     g_h);
    cudaGetSymbolAddress((void**)&pff,    g_ff);
    cudaGetSymbolAddress((void**)&px2,    g_x2);
    cudaGetSymbolAddress((void**)&pwq,    g_wq);
    cudaGetSymbolAddress((void**)&pwk,    g_wk);
    cudaGetSymbolAddress((void**)&pwv,    g_wv);
    cudaGetSymbolAddress((void**)&pscores,g_scores);

    // split buffers alias the scores pool (time-disjoint with score usage)
    __nv_bfloat16* pbhi = (__nv_bfloat16*)((char*)pscores + kOffBhi);
    __nv_bfloat16* pblo = (__nv_bfloat16*)((char*)pscores + kOffBlo);
    __nv_bfloat16* pahi = (__nv_bfloat16*)((char*)pscores + kOffAhi);
    __nv_bfloat16* palo = (__nv_bfloat16*)((char*)pscores + kOffAlo);

    // raise dynamic smem limit for the fused GEMM (host-side attribute; capture-safe)
    cudaFuncSetAttribute(hgemm_fused<0>, cudaFuncAttributeMaxDynamicSharedMemorySize, kGemmSmem);
    cudaFuncSetAttribute(hgemm_fused<1>, cudaFuncAttributeMaxDynamicSharedMemorySize, kGemmSmem);
    cudaFuncSetAttribute(hgemm_fused<2>, cudaFuncAttributeMaxDynamicSharedMemorySize, kGemmSmem);

    dim3 t328(32, 8);

    // 1. positional encoding + embedding
    pe_kernel<<<1, 1024>>>();
    embed_kernel<<<kROWS, 256>>>(tok, emb);

    // 2. repack per-head QKV weights into [HID, HID] fp32
    pack_w_kernel<<<(kHID * kHID + 255) / 256, 256>>>(Wq, pwq);
    pack_w_kernel<<<(kHID * kHID + 255) / 256, 256>>>(Wk, pwk);
    pack_w_kernel<<<(kHID * kHID + 255) / 256, 256>>>(Wv, pwv);

    // 3. QKV projections on tensor cores (fused hi/lo split), scatter epilogue
    split4_kernel<<<(kROWS * kHID / 4 + 255) / 256, 256>>>(px, pahi, palo, kROWS * kHID / 4);
    dim3 gQ(kHID / 128, (kROWS + 127) / 128);
    splitT_kernel<<<dim3(kHID / 32, kHID / 32), t328>>>(pwq, pbhi, pblo, kHID, kHID);
    hgemm_fused<2><<<gQ, 256, kGemmSmem>>>(pahi, palo, pbhi, pblo, bq, pq, kROWS, kHID, kHID);
    splitT_kernel<<<dim3(kHID / 32, kHID / 32), t328>>>(pwk, pbhi, pblo, kHID, kHID);
    hgemm_fused<2><<<gQ, 256, kGemmSmem>>>(pahi, palo, pbhi, pblo, bk, pk, kROWS, kHID, kHID);
    splitT_kernel<<<dim3(kHID / 32, kHID / 32), t328>>>(pwv, pbhi, pblo, kHID, kHID);
    hgemm_fused<2><<<gQ, 256, kGemmSmem>>>(pahi, palo, pbhi, pblo, bv, pv, kROWS, kHID, kHID);

    // 4. attention (fp32; scores OVERWRITE the split buffers — dead here)
    scores_kernel<<<dim3(16, 16, kBH), 256>>>();
    softmax_kernel<<<kBH * kS, 256>>>();
    pv_kernel<<<dim3(16, kBH), 256>>>();

    // 5. output projection + residual + LN1 (splits overwrite scores — dead after pv)
    split4_kernel<<<(kROWS * kHID / 4 + 255) / 256, 256>>>(pattn, pahi, palo, kROWS * kHID / 4);
    splitT_kernel<<<dim3(kHID / 32, kHID / 32), t328>>>(Wc, pbhi, pblo, kHID, kHID);
    hgemm_fused<0><<<dim3(kHID / 128, (kROWS + 127) / 128), 256, kGemmSmem>>>(pahi, palo, pbhi, pblo, bc, pff, kROWS, kHID, kHID);
    add_ln_kernel<<<kROWS, 256>>>(px, pff, ln1g, ln1b, px1);

    // 6. feed-forward + residual + LN2
    split4_kernel<<<(kROWS * kHID / 4 + 255) / 256, 256>>>(px1, pahi, palo, kROWS * kHID / 4);
    splitT_kernel<<<dim3(kFFH / 32, kHID / 32), t328>>>(W1, pbhi, pblo, kHID, kFFH);
    hgemm_fused<1><<<dim3(kFFH / 128, (kROWS + 127) / 128), 256, kGemmSmem>>>(pahi, palo, pbhi, pblo, b1, ph, kROWS, kFFH, kHID);
    split4_kernel<<<(kROWS * kFFH / 4 + 255) / 256, 256>>>(ph, pahi, palo, kROWS * kFFH / 4);
    splitT_kernel<<<dim3(kHID / 32, kFFH / 32), t328>>>(W2, pbhi, pblo, kFFH, kHID);
    hgemm_fused<0><<<dim3(kHID / 128, (kROWS + 127) / 128), 256, kGemmSmem>>>(pahi, palo, pbhi, pblo, b2, pff, kROWS, kHID, kFFH);
    add_ln_kernel<<<kROWS, 256>>>(px1, pff, ln2g, ln2b, px2);

    // 7. logits (dominant GEMM) on tensor cores -> d_out
    split4_kernel<<<(kROWS * kHID / 4 + 255) / 256, 256>>>(px2, pahi, palo, kROWS * kHID / 4);
    splitT_kernel<<<dim3(kVOC / 32, kHID / 32), t328>>>(Wlog, pbhi, pblo, kHID, kVOC);
    hgemm_fused<0><<<dim3(kVOC / 128, (kROWS + 127) / 128), 256, kGemmSmem>>>(pahi, palo, pbhi, pblo, blog, out, kROWS, kVOC, kHID);

    (void)in_sizes; (void)n_in; (void)out_size;
}

// round 8
// speedup vs baseline: 2.4313x; 1.0571x over previous
#include <cuda_runtime.h>
#include <cuda_bf16.h>
#include <math.h>
#include <stdint.h>

// ---------------- problem constants ----------------
constexpr int kB    = 4;
constexpr int kS    = 1000;
constexpr int kHID  = 1024;
constexpr int kNH   = 16;
constexpr int kDK   = 64;
constexpr int kFFH  = 2048;
constexpr int kVOC  = 32000;
constexpr int kROWS = kB * kS;     // 4000
constexpr int kBH   = kB * kNH;    // 64

// ---------------- device scratch (no allocations allowed) ----------------
__device__ float g_pe[kHID];
__device__ float g_x   [kROWS * kHID];
__device__ float g_q   [kBH * kS * kDK];
__device__ float g_k   [kBH * kS * kDK];
__device__ float g_v   [kBH * kS * kDK];
__device__ float g_attn[kROWS * kHID];
__device__ float g_x1  [kROWS * kHID];
__device__ float g_h   [kROWS * kFFH];
__device__ float g_ff  [kROWS * kHID];
__device__ float g_x2  [kROWS * kHID];
__device__ float g_wq  [kHID * kHID];
__device__ float g_wk  [kHID * kHID];
__device__ float g_wv  [kHID * kHID];

// bf16 split pool (164 MB): bhi | blo | ahi | alo
constexpr size_t kOffBhi = 0;
constexpr size_t kOffBlo = (size_t)kHID * kVOC * 2;
constexpr size_t kOffAhi = kOffBlo + (size_t)kHID * kVOC * 2;
constexpr size_t kOffAlo = kOffAhi + (size_t)kROWS * kFFH * 2;
constexpr size_t kPoolSz = kOffAlo + (size_t)kROWS * kFFH * 2;
__device__ __align__(256) char g_pool[kPoolSz];

// ---------------- positional encoding (source-bug constant vector) ----------------
__global__ void pe_kernel() {
    int c = threadIdx.x;                     // 0..1023
    int i = c & ~1;
    double tmp = 999.0 * exp(-(double)i / 1024.0 * log(10000.0));
    g_pe[c] = (c & 1) ? (float)cos(tmp) : (float)sin(tmp);
}

// x[row] = emb[token[row]] + pe
__global__ void embed_kernel(const int* __restrict__ tok, const float* __restrict__ emb) {
    int row = blockIdx.x;
    int t = tok[row];
    const float4* e = (const float4*)(emb + (size_t)t * kHID);
    const float4* p = (const float4*)g_pe;
    float4* xo = (float4*)(g_x + (size_t)row * kHID);
    int c = threadIdx.x;
    float4 a = e[c], b = p[c];
    xo[c] = make_float4(a.x + b.x, a.y + b.y, a.z + b.z, a.w + b.w);
}

// repack W[n][h][d] -> Wp[h][n*64+d]
__global__ void pack_w_kernel(const float* __restrict__ W, float* __restrict__ out) {
    int idx = blockIdx.x * blockDim.x + threadIdx.x;
    if (idx < kHID * kHID) {
        int h = idx >> 10;
        int col = idx & 1023;
        int n = col >> 6, d = col & 63;
        out[idx] = W[((size_t)n * kHID + h) * kDK + d];
    }
}

// ---------------- fp32 -> bf16 hi/lo split (row-major, elementwise, x4) ----------------
__global__ void split4_kernel(const float* __restrict__ in,
                              __nv_bfloat16* __restrict__ hi,
                              __nv_bfloat16* __restrict__ lo, int n4) {
    int i = blockIdx.x * 256 + threadIdx.x;
    if (i >= n4) return;
    float4 x = ((const float4*)in)[i];
    __nv_bfloat16 h0 = __float2bfloat16(x.x), h1 = __float2bfloat16(x.y);
    __nv_bfloat16 h2 = __float2bfloat16(x.z), h3 = __float2bfloat16(x.w);
    __nv_bfloat16 l0 = __float2bfloat16(x.x - __bfloat162float(h0));
    __nv_bfloat16 l1 = __float2bfloat16(x.y - __bfloat162float(h1));
    __nv_bfloat16 l2 = __float2bfloat16(x.z - __bfloat162float(h2));
    __nv_bfloat16 l3 = __float2bfloat16(x.w - __bfloat162float(h3));
    __nv_bfloat162* hp = (__nv_bfloat162*)hi;
    __nv_bfloat162* lp = (__nv_bfloat162*)lo;
    hp[i*2+0] = __nv_bfloat162(h0, h1); hp[i*2+1] = __nv_bfloat162(h2, h3);
    lp[i*2+0] = __nv_bfloat162(l0, l1); lp[i*2+1] = __nv_bfloat162(l2, l3);
}

// ---------------- fp32 [K,N] -> bf16 hi/lo [N,K] (transpose + split) ----------------
__global__ void splitT_kernel(const float* __restrict__ in,
                              __nv_bfloat16* __restrict__ hi,
                              __nv_bfloat16* __restrict__ lo, int K, int N) {
    __shared__ float t[32][33];
    int n0 = blockIdx.x * 32, k0 = blockIdx.y * 32;
    int tx = threadIdx.x;
#pragma unroll
    for (int i = threadIdx.y; i < 32; i += 8)
        t[i][tx] = in[(size_t)(k0 + i) * N + n0 + tx];
    __syncthreads();
#pragma unroll
    for (int i = threadIdx.y; i < 32; i += 8) {
        float x = t[tx][i];
        __nv_bfloat16 h = __float2bfloat16(x);
        size_t o = (size_t)(n0 + i) * K + k0 + tx;
        hi[o] = h;
        lo[o] = __float2bfloat16(x - __bfloat162float(h));
    }
}

// ---------------- cp.async helpers ----------------
__device__ __forceinline__ void cp16(uint32_t dst, const void* src, bool full) {
    int sz = full ? 16 : 0;
    asm volatile("cp.async.cg.shared.global [%0], [%1], 16, %2;"
                 :: "r"(dst), "l"(src), "r"(sz) : "memory");
}
__device__ __forceinline__ void cp_commit() {
    asm volatile("cp.async.commit_group;" ::: "memory");
}

// ---------------- fused bf16-split tensor-core GEMM (single K pass, 3 MMAs/tile) ----------------
constexpr int kPITCH = 40;
constexpr int kArrSz = 128 * kPITCH;
constexpr int kGemmSmem = 2 * 4 * kArrSz * 2;

template<int EPI>
__global__ __launch_bounds__(256)
void hgemm_fused(const __nv_bfloat16* __restrict__ aHi, const __nv_bfloat16* __restrict__ aLo,
                 const __nv_bfloat16* __restrict__ bHi, const __nv_bfloat16* __restrict__ bLo,
                 const float* __restrict__ bias, float* __restrict__ C,
                 int M, int N, int K) {
    extern __shared__ __align__(16) __nv_bfloat16 dynsm[];
    uint32_t smbase;
    { uint64_t t64; asm("cvta.to.shared.u64 %0, %1;" : "=l"(t64) : "l"(dynsm)); smbase = (uint32_t)t64; }

    int tid = threadIdx.x;
    int wid = tid >> 5, lane = tid & 31;
    int wm = wid >> 2, wn = wid & 3;
    int r = lane >> 2, c2 = (lane & 3) * 2;
    int m0 = blockIdx.y * 128, n0 = blockIdx.x * 128;

    const __nv_bfloat16* gsrc[4] = {aHi, aLo, bHi, bLo};

    auto issue_tile = [&](int stage, int k0) {
#pragma unroll
        for (int arr = 0; arr < 4; arr++) {
            const __nv_bfloat16* gp = gsrc[arr];
            bool isA = arr < 2;
#pragma unroll
            for (int i = 0; i < 2; i++) {
                int idx = tid + i * 256;
                int row = idx >> 2;
                int c4 = (idx & 3) * 8;
                int grow = (isA ? m0 : n0) + row;
                bool ok = isA ? (grow < M) : true;
                const void* src = gp + (size_t)(ok ? grow : 0) * K + k0 + c4;
                uint32_t dst = smbase + (uint32_t)(((stage * 4 + arr) * kArrSz + row * kPITCH + c4) * 2);
                cp16(dst, src, ok);
            }
        }
    };

    float acc[4][4][4] = {};

    issue_tile(0, 0);
    cp_commit();

    int stage = 0;
    for (int k0 = 0; k0 < K; k0 += 32) {
        bool hasNext = (k0 + 32) < K;
        if (hasNext) {
            issue_tile(stage ^ 1, k0 + 32);
            cp_commit();
            asm volatile("cp.async.wait_group 1;" ::: "memory");
        } else {
            asm volatile("cp.async.wait_group 0;" ::: "memory");
        }
        __syncthreads();

        const __nv_bfloat16* sAhi = dynsm + (stage * 4 + 0) * kArrSz;
        const __nv_bfloat16* sAlo = dynsm + (stage * 4 + 1) * kArrSz;
        const __nv_bfloat16* sBhi = dynsm + (stage * 4 + 2) * kArrSz;
        const __nv_bfloat16* sBlo = dynsm + (stage * 4 + 3) * kArrSz;

#pragma unroll
        for (int ks = 0; ks < 32; ks += 16) {
            uint32_t ahi[4][4], alo[4][4], bhi[4][2], blo[4][2];
#pragma unroll
            for (int mi = 0; mi < 4; mi++) {
                int rr = (wm * 64 + mi * 16 + r) * kPITCH + ks + c2;
                ahi[mi][0] = *(const uint32_t*)&sAhi[rr];
                ahi[mi][1] = *(const uint32_t*)&sAhi[rr + 8 * kPITCH];
                ahi[mi][2] = *(const uint32_t*)&sAhi[rr + 8];
                ahi[mi][3] = *(const uint32_t*)&sAhi[rr + 8 * kPITCH + 8];
                alo[mi][0] = *(const uint32_t*)&sAlo[rr];
                alo[mi][1] = *(const uint32_t*)&sAlo[rr + 8 * kPITCH];
                alo[mi][2] = *(const uint32_t*)&sAlo[rr + 8];
                alo[mi][3] = *(const uint32_t*)&sAlo[rr + 8 * kPITCH + 8];
            }
#pragma unroll
            for (int ni = 0; ni < 4; ni++) {
                int rr = (wn * 32 + ni * 8 + r) * kPITCH + ks + c2;
                bhi[ni][0] = *(const uint32_t*)&sBhi[rr];
                bhi[ni][1] = *(const uint32_t*)&sBhi[rr + 8];
                blo[ni][0] = *(const uint32_t*)&sBlo[rr];
                blo[ni][1] = *(const uint32_t*)&sBlo[rr + 8];
            }
#define MMA(A0,A1,A2,A3,B0,B1,ACC) \
    asm volatile("mma.sync.aligned.m16n8k16.row.col.f32.bf16.bf16.f32 " \
                 "{%0,%1,%2,%3}, {%4,%5,%6,%7}, {%8,%9}, {%0,%1,%2,%3};" \
                 : "+f"(ACC[0]), "+f"(ACC[1]), "+f"(ACC[2]), "+f"(ACC[3]) \
                 : "r"(A0), "r"(A1), "r"(A2), "r"(A3), "r"(B0), "r"(B1))
#pragma unroll
            for (int mi = 0; mi < 4; mi++)
#pragma unroll
                for (int ni = 0; ni < 4; ni++) {
                    MMA(ahi[mi][0], ahi[mi][1], ahi[mi][2], ahi[mi][3],
                        bhi[ni][0], bhi[ni][1], acc[mi][ni]);
                    MMA(ahi[mi][0], ahi[mi][1], ahi[mi][2], ahi[mi][3],
                        blo[ni][0], blo[ni][1], acc[mi][ni]);
                    MMA(alo[mi][0], alo[mi][1], alo[mi][2], alo[mi][3],
                        bhi[ni][0], bhi[ni][1], acc[mi][ni]);
                }
#undef MMA
        }
        __syncthreads();
        stage ^= 1;
    }

#pragma unroll
    for (int mi = 0; mi < 4; mi++) {
#pragma unroll
        for (int half = 0; half < 2; half++) {
            int row = m0 + wm * 64 + mi * 16 + r + half * 8;
            if (row >= M) continue;
#pragma unroll
            for (int ni = 0; ni < 4; ni++) {
                int col = n0 + wn * 32 + ni * 8 + c2;
                float v0 = acc[mi][ni][half * 2 + 0] + bias[col];
                float v1 = acc[mi][ni][half * 2 + 1] + bias[col + 1];
                if (EPI == 1) { v0 = fmaxf(v0, 0.f); v1 = fmaxf(v1, 0.f); }
                if (EPI == 2) {
                    int b = row / kS, s = row % kS;
                    int n = col >> 6, d = col & 63;
                    size_t base = (((size_t)(b * kNH + n)) * kS + s) * kDK + d;
                    C[base] = v0; C[base + 1] = v1;
                } else {
                    *(float2*)&C[(size_t)row * N + col] = make_float2(v0, v1);
                }
            }
        }
    }
}

// ---------------- fused flash attention ----------------
// scores[s][t] = floor((k_s . q_t)/8), causal mask t<=s, online softmax, PV accumulate.
// grid(16 s-tiles, kBH), block 256 (16x16 threads, 4x4 per thread).
// dynamic smem: Ks,Qs,Vs,Ps each [64][68] fp32 = 69632 B.
constexpr int kAttnSmem = 4 * 64 * 68 * 4;

__global__ __launch_bounds__(256)
void flash_attn_kernel() {
    extern __shared__ float asm_[];
    float (*Ks)[68] = (float(*)[68])asm_;                 // [d][s]
    float (*Qs)[68] = (float(*)[68])(asm_ + 64 * 68);     // [d][t]
    float (*Vs)[68] = (float(*)[68])(asm_ + 2 * 64 * 68); // [t][d]
    float (*Ps)[68] = (float(*)[68])(asm_ + 3 * 64 * 68); // [t][s]

    int bh = blockIdx.y;
    int s0 = blockIdx.x * 64;
    const float* kp = g_k + (size_t)bh * kS * kDK;
    const float* qp = g_q + (size_t)bh * kS * kDK;
    const float* vp = g_v + (size_t)bh * kS * kDK;
    int tid = threadIdx.x;
    int tr = tid >> 4, tc = tid & 15;

    // load K tile once: Ks[d][s]
#pragma unroll
    for (int i = 0; i < 4; i++) {
        int idx = tid + i * 256;
        int r = idx >> 4;                 // 0..63 (s)
        int c = (idx & 15) << 2;          // 0..60 (d)
        float4 vk = (s0 + r < kS) ? *(const float4*)&kp[(size_t)(s0 + r) * kDK + c]
                                  : make_float4(0.f, 0.f, 0.f, 0.f);
        Ks[c + 0][r] = vk.x; Ks[c + 1][r] = vk.y; Ks[c + 2][r] = vk.z; Ks[c + 3][r] = vk.w;
    }

    float m_run[4], l_run[4], acc[4][4];
#pragma unroll
    for (int i = 0; i < 4; i++) {
        m_run[i] = -1e30f; l_run[i] = 0.f;
#pragma unroll
        for (int j = 0; j < 4; j++) acc[i][j] = 0.f;
    }

    for (int t0 = 0; t0 <= s0; t0 += 64) {
        __syncthreads();   // previous iteration finished reading Qs/Vs/Ps
        // load Q [d][t], V [t][d]
#pragma unroll
        for (int i = 0; i < 4; i++) {
            int idx = tid + i * 256;
            int r = idx >> 4;
            int c = (idx & 15) << 2;
            bool ok = (t0 + r < kS);
            float4 vq = ok ? *(const float4*)&qp[(size_t)(t0 + r) * kDK + c]
                           : make_float4(0.f, 0.f, 0.f, 0.f);
            Qs[c + 0][r] = vq.x; Qs[c + 1][r] = vq.y; Qs[c + 2][r] = vq.z; Qs[c + 3][r] = vq.w;
            float4 vv = ok ? *(const float4*)&vp[(size_t)(t0 + r) * kDK + c]
                           : make_float4(0.f, 0.f, 0.f, 0.f);
            *(float4*)&Vs[r][c] = vv;
        }
        __syncthreads();

        // scores S[i][j] = k_{s0+tr*4+i} . q_{t0+tc*4+j}
        float S[4][4] = {};
#pragma unroll
        for (int d = 0; d < 64; d++) {
            float ra[4], rb[4];
#pragma unroll
            for (int i = 0; i < 4; i++) ra[i] = Ks[d][tr * 4 + i];
#pragma unroll
            for (int j = 0; j < 4; j++) rb[j] = Qs[d][tc * 4 + j];
#pragma unroll
            for (int i = 0; i < 4; i++)
#pragma unroll
                for (int j = 0; j < 4; j++) S[i][j] += ra[i] * rb[j];
        }
        // floor + causal mask
#pragma unroll
        for (int i = 0; i < 4; i++) {
            int s = s0 + tr * 4 + i;
#pragma unroll
            for (int j = 0; j < 4; j++) {
                int t = t0 + tc * 4 + j;
                S[i][j] = (t > s) ? -INFINITY : floorf(S[i][j] * 0.125f);
            }
        }
        // online softmax update
        float corr[4];
#pragma unroll
        for (int i = 0; i < 4; i++) {
            float mt = fmaxf(fmaxf(S[i][0], S[i][1]), fmaxf(S[i][2], S[i][3]));
#pragma unroll
            for (int o = 8; o; o >>= 1) mt = fmaxf(mt, __shfl_xor_sync(0xffffffffu, mt, o, 16));
            float nm = fmaxf(m_run[i], mt);
            corr[i] = expf(m_run[i] - nm);
            m_run[i] = nm;
            float ls = 0.f;
#pragma unroll
            for (int j = 0; j < 4; j++) {
                float p = expf(S[i][j] - nm);   // masked -> exp(-inf)=0
                S[i][j] = p;
                ls += p;
            }
#pragma unroll
            for (int o = 8; o; o >>= 1) ls += __shfl_xor_sync(0xffffffffu, ls, o, 16);
            l_run[i] = l_run[i] * corr[i] + ls;
#pragma unroll
            for (int j = 0; j < 4; j++) acc[i][j] *= corr[i];
        }
        // store P as [t][s]
#pragma unroll
        for (int i = 0; i < 4; i++)
#pragma unroll
            for (int j = 0; j < 4; j++)
                Ps[tc * 4 + j][tr * 4 + i] = S[i][j];
        __syncthreads();

        // acc[i][j] += sum_t Ps[t][s_i] * Vs[t][d_j]
#pragma unroll
        for (int k = 0; k < 64; k++) {
            float ra[4], rb[4];
#pragma unroll
            for (int i = 0; i < 4; i++) ra[i] = Ps[k][tr * 4 + i];
#pragma unroll
            for (int j = 0; j < 4; j++) rb[j] = Vs[k][tc * 4 + j];
#pragma unroll
            for (int i = 0; i < 4; i++)
#pragma unroll
                for (int j = 0; j < 4; j++) acc[i][j] += ra[i] * rb[j];
        }
    }

    // normalize + write to concat-head layout
    int b = bh >> 4, n = bh & 15;
#pragma unroll
    for (int i = 0; i < 4; i++) {
        int s = s0 + tr * 4 + i;
        if (s >= kS) continue;
        float inv = 1.f / l_run[i];
#pragma unroll
        for (int j = 0; j < 4; j++) {
            g_attn[((size_t)(b * kS + s)) * kHID + n * kDK + tc * 4 + j] = acc[i][j] * inv;
        }
    }
}

// ---------------- out = LayerNorm(x + delta) * g + b ----------------
__global__ __launch_bounds__(256)
void add_ln_kernel(const float* __restrict__ xin, const float* __restrict__ dl,
                   const float* __restrict__ g, const float* __restrict__ b,
                   float* __restrict__ out) {
    int row = blockIdx.x;
    int tid = threadIdx.x;
    const float* xr = xin + (size_t)row * kHID;
    const float* dr = dl  + (size_t)row * kHID;
    __shared__ float red[256];

    float v[4]; float ls = 0.f;
#pragma unroll
    for (int i = 0; i < 4; i++) { int c = tid + i * 256; v[i] = xr[c] + dr[c]; ls += v[i]; }
    red[tid] = ls; __syncthreads();
    for (int o = 128; o; o >>= 1) { if (tid < o) red[tid] += red[tid + o]; __syncthreads(); }
    float mu = red[0] * (1.f / kHID);
    __syncthreads();

    float lv = 0.f;
#pragma unroll
    for (int i = 0; i < 4; i++) { float d = v[i] - mu; lv += d * d; }
    red[tid] = lv; __syncthreads();
    for (int o = 128; o; o >>= 1) { if (tid < o) red[tid] += red[tid + o]; __syncthreads(); }
    float rstd = 1.f / sqrtf(red[0] * (1.f / kHID) + 1e-5f);

    float* orow = out + (size_t)row * kHID;
#pragma unroll
    for (int i = 0; i < 4; i++) {
        int c = tid + i * 256;
        orow[c] = (v[i] - mu) * rstd * g[c] + b[c];
    }
}

// ---------------- launcher ----------------
extern "C" void kernel_launch(void* const* d_in, const int* in_sizes, int n_in,
                              void* d_out, int out_size) {
    const int*   tok  = (const int*)  d_in[0];
    const float* emb  = (const float*)d_in[1];
    const float* Wq   = (const float*)d_in[2];
    const float* bq   = (const float*)d_in[3];
    const float* Wk   = (const float*)d_in[4];
    const float* bk   = (const float*)d_in[5];
    const float* Wv   = (const float*)d_in[6];
    const float* bv   = (const float*)d_in[7];
    const float* Wc   = (const float*)d_in[8];
    const float* bc   = (const float*)d_in[9];
    const float* ln1g = (const float*)d_in[10];
    const float* ln1b = (const float*)d_in[11];
    const float* W1   = (const float*)d_in[12];
    const float* b1   = (const float*)d_in[13];
    const float* W2   = (const float*)d_in[14];
    const float* b2   = (const float*)d_in[15];
    const float* ln2g = (const float*)d_in[16];
    const float* ln2b = (const float*)d_in[17];
    const float* Wlog = (const float*)d_in[18];
    const float* blog = (const float*)d_in[19];
    float* out = (float*)d_out;

    float *px, *pq, *pk, *pv, *pattn, *px1, *ph, *pff, *px2, *pwq, *pwk, *pwv;
    char* ppool;
    cudaGetSymbolAddress((void**)&px,    g_x);
    cudaGetSymbolAddress((void**)&pq,    g_q);
    cudaGetSymbolAddress((void**)&pk,    g_k);
    cudaGetSymbolAddress((void**)&pv,    g_v);
    cudaGetSymbolAddress((void**)&pattn, g_attn);
    cudaGetSymbolAddress((void**)&px1,   g_x1);
    cudaGetSymbolAddress((void**)&ph,    g_h);
    cudaGetSymbolAddress((void**)&pff,   g_ff);
    cudaGetSymbolAddress((void**)&px2,   g_x2);
    cudaGetSymbolAddress((void**)&pwq,   g_wq);
    cudaGetSymbolAddress((void**)&pwk,   g_wk);
    cudaGetSymbolAddress((void**)&pwv,   g_wv);
    cudaGetSymbolAddress((void**)&ppool, g_pool);

    __nv_bfloat16* pbhi = (__nv_bfloat16*)(ppool + kOffBhi);
    __nv_bfloat16* pblo = (__nv_bfloat16*)(ppool + kOffBlo);
    __nv_bfloat16* pahi = (__nv_bfloat16*)(ppool + kOffAhi);
    __nv_bfloat16* palo = (__nv_bfloat16*)(ppool + kOffAlo);

    cudaFuncSetAttribute(hgemm_fused<0>, cudaFuncAttributeMaxDynamicSharedMemorySize, kGemmSmem);
    cudaFuncSetAttribute(hgemm_fused<1>, cudaFuncAttributeMaxDynamicSharedMemorySize, kGemmSmem);
    cudaFuncSetAttribute(hgemm_fused<2>, cudaFuncAttributeMaxDynamicSharedMemorySize, kGemmSmem);
    cudaFuncSetAttribute(flash_attn_kernel, cudaFuncAttributeMaxDynamicSharedMemorySize, kAttnSmem);

    dim3 t328(32, 8);

    // 1. positional encoding + embedding
    pe_kernel<<<1, 1024>>>();
    embed_kernel<<<kROWS, 256>>>(tok, emb);

    // 2. repack per-head QKV weights into [HID, HID] fp32
    pack_w_kernel<<<(kHID * kHID + 255) / 256, 256>>>(Wq, pwq);
    pack_w_kernel<<<(kHID * kHID + 255) / 256, 256>>>(Wk, pwk);
    pack_w_kernel<<<(kHID * kHID + 255) / 256, 256>>>(Wv, pwv);

    // 3. QKV projections on tensor cores (fused hi/lo split), scatter epilogue
    split4_kernel<<<(kROWS * kHID / 4 + 255) / 256, 256>>>(px, pahi, palo, kROWS * kHID / 4);
    dim3 gQ(kHID / 128, (kROWS + 127) / 128);
    splitT_kernel<<<dim3(kHID / 32, kHID / 32), t328>>>(pwq, pbhi, pblo, kHID, kHID);
    hgemm_fused<2><<<gQ, 256, kGemmSmem>>>(pahi, palo, pbhi, pblo, bq, pq, kROWS, kHID, kHID);
    splitT_kernel<<<dim3(kHID / 32, kHID / 32), t328>>>(pwk, pbhi, pblo, kHID, kHID);
    hgemm_fused<2><<<gQ, 256, kGemmSmem>>>(pahi, palo, pbhi, pblo, bk, pk, kROWS, kHID, kHID);
    splitT_kernel<<<dim3(kHID / 32, kHID / 32), t328>>>(pwv, pbhi, pblo, kHID, kHID);
    hgemm_fused<2><<<gQ, 256, kGemmSmem>>>(pahi, palo, pbhi, pblo, bv, pv, kROWS, kHID, kHID);

    // 4. fused flash attention (fp32 — protects floor() discontinuity)
    flash_attn_kernel<<<dim3(16, kBH), 256, kAttnSmem>>>();

    // 5. output projection + residual + LN1
    split4_kernel<<<(kROWS * kHID / 4 + 255) / 256, 256>>>(pattn, pahi, palo, kROWS * kHID / 4);
    splitT_kernel<<<dim3(kHID / 32, kHID / 32), t328>>>(Wc, pbhi, pblo, kHID, kHID);
    hgemm_fused<0><<<dim3(kHID / 128, (kROWS + 127) / 128), 256, kGemmSmem>>>(pahi, palo, pbhi, pblo, bc, pff, kROWS, kHID, kHID);
    add_ln_kernel<<<kROWS, 256>>>(px, pff, ln1g, ln1b, px1);

    // 6. feed-forward + residual + LN2
    split4_kernel<<<(kROWS * kHID / 4 + 255) / 256, 256>>>(px1, pahi, palo, kROWS * kHID / 4);
    splitT_kernel<<<dim3(kFFH / 32, kHID / 32), t328>>>(W1, pbhi, pblo, kHID, kFFH);
    hgemm_fused<1><<<dim3(kFFH / 128, (kROWS + 127) / 128), 256, kGemmSmem>>>(pahi, palo, pbhi, pblo, b1, ph, kROWS, kFFH, kHID);
    split4_kernel<<<(kROWS * kFFH / 4 + 255) / 256, 256>>>(ph, pahi, palo, kROWS * kFFH / 4);
    splitT_kernel<<<dim3(kHID / 32, kFFH / 32), t328>>>(W2, pbhi, pblo, kFFH, kHID);
    hgemm_fused<0><<<dim3(kHID / 128, (kROWS + 127) / 128), 256, kGemmSmem>>>(pahi, palo, pbhi, pblo, b2, pff, kROWS, kHID, kFFH);
    add_ln_kernel<<<kROWS, 256>>>(px1, pff, ln2g, ln2b, px2);

    // 7. logits (dominant GEMM) on tensor cores -> d_out
    split4_kernel<<<(kROWS * kHID / 4 + 255) / 256, 256>>>(px2, pahi, palo, kROWS * kHID / 4);
    splitT_kernel<<<dim3(kVOC / 32, kHID / 32), t328>>>(Wlog, pbhi, pblo, kHID, kVOC);
    hgemm_fused<0><<<dim3(kVOC / 128, (kROWS + 127) / 128), 256, kGemmSmem>>>(pahi, palo, pbhi, pblo, blog, out, kROWS, kVOC, kHID);

    (void)in_sizes; (void)n_in; (void)out_size;
}